// round 14
// baseline (speedup 1.0000x reference)
#include <cuda_runtime.h>
#include <cuda_bf16.h>
#include <cuda_fp16.h>
#include <stdint.h>

#define DM 1024
#define NH 16
#define DK 64
#define NB 4
#define SQ 2048
#define MROWS (NB * SQ)                 // 8192
#define YSZ ((size_t)MROWS * DM)
#define ABH ((size_t)SQ * SQ)

typedef __nv_bfloat16 bf16;

// ---------------------------------------------------------------------------
// Scratch (allocation-free rule: __device__ globals). 16-bit buffers are
// dtype-agnostic byte storage (bf16 or fp16 depending on stage).
// ---------------------------------------------------------------------------
__device__ bf16 g_xh[MROWS * DM],  g_xl[MROWS * DM];    // Q input (bf16 hi/lo)
__device__ bf16 g_x2h[MROWS * DM], g_x2l[MROWS * DM];   // K input
__device__ bf16 g_x3h[MROWS * DM], g_x3l[MROWS * DM];   // V input
__device__ bf16 g_ch[MROWS * DM],  g_cl[MROWS * DM];    // ctx output (fp16 hi/lo)
__device__ bf16 g_wh[DM * DM],  g_wl[DM * DM];          // Wq (bf16 hi/lo)
__device__ bf16 g_w2h[DM * DM], g_w2l[DM * DM];         // Wk
__device__ bf16 g_w3h[DM * DM], g_w3l[DM * DM];         // Wv
__device__ bf16 g_woh[DM * DM];                         // Wo (fp16 hi)
__device__ bf16 g_qh[MROWS * DM], g_ql[MROWS * DM];     // q (bf16 hi/lo)
__device__ bf16 g_kh[MROWS * DM], g_kl[MROWS * DM];     // k (bf16 hi/lo)
__device__ bf16 g_vh[MROWS * DM];                       // v (fp16 hi only)
__device__ float g_o[MROWS * DM];

// ---------------------------------------------------------------------------
// Baseline-PTX helpers (sm_80-era: legal on plain compute_103)
// ---------------------------------------------------------------------------
__device__ __forceinline__ uint32_t smem_u32(const void* p) {
    uint32_t a;
    asm("{ .reg .u64 t; cvta.to.shared.u64 t, %1; cvt.u32.u64 %0, t; }"
        : "=r"(a) : "l"(p));
    return a;
}

__device__ __forceinline__ void mma16816(float* c, const uint32_t* a, const uint32_t* b) {
    asm volatile(
        "mma.sync.aligned.m16n8k16.row.col.f32.bf16.bf16.f32 "
        "{%0,%1,%2,%3}, {%4,%5,%6,%7}, {%8,%9}, {%0,%1,%2,%3};"
        : "+f"(c[0]), "+f"(c[1]), "+f"(c[2]), "+f"(c[3])
        : "r"(a[0]), "r"(a[1]), "r"(a[2]), "r"(a[3]), "r"(b[0]), "r"(b[1]));
}
__device__ __forceinline__ void mma16816h(float* c, const uint32_t* a, const uint32_t* b) {
    asm volatile(
        "mma.sync.aligned.m16n8k16.row.col.f32.f16.f16.f32 "
        "{%0,%1,%2,%3}, {%4,%5,%6,%7}, {%8,%9}, {%0,%1,%2,%3};"
        : "+f"(c[0]), "+f"(c[1]), "+f"(c[2]), "+f"(c[3])
        : "r"(a[0]), "r"(a[1]), "r"(a[2]), "r"(a[3]), "r"(b[0]), "r"(b[1]));
}

__device__ __forceinline__ void ldmA(uint32_t* r, uint32_t addr) {
    asm volatile("ldmatrix.sync.aligned.m8n8.x4.shared.b16 {%0,%1,%2,%3}, [%4];"
        : "=r"(r[0]), "=r"(r[1]), "=r"(r[2]), "=r"(r[3]) : "r"(addr));
}
__device__ __forceinline__ void ldmB(uint32_t* r, uint32_t addr) {
    asm volatile("ldmatrix.sync.aligned.m8n8.x2.shared.b16 {%0,%1}, [%2];"
        : "=r"(r[0]), "=r"(r[1]) : "r"(addr));
}
__device__ __forceinline__ void ldmBT(uint32_t* r, uint32_t addr) {
    asm volatile("ldmatrix.sync.aligned.m8n8.x2.trans.shared.b16 {%0,%1}, [%2];"
        : "=r"(r[0]), "=r"(r[1]) : "r"(addr));
}

__device__ __forceinline__ void cp16(uint32_t dst, const void* src) {
    asm volatile("cp.async.cg.shared.global [%0], [%1], 16;" :: "r"(dst), "l"(src));
}
__device__ __forceinline__ void cp_commit() {
    asm volatile("cp.async.commit_group;" ::: "memory");
}
template <int N>
__device__ __forceinline__ void cp_wait() {
    asm volatile("cp.async.wait_group %0;" :: "n"(N) : "memory");
}

// Tile rows are 64 halfwords = 128B, XOR-swizzled in 16B granules.
__device__ __forceinline__ uint32_t swz(int row, int c16) {
    return (uint32_t)(row * 128 + ((c16 ^ (row & 7)) << 4));
}
__device__ __forceinline__ uint32_t addrA(uint32_t base, int m_base, int kk, int lane) {
    int mat = lane >> 3;
    int row = m_base + (lane & 7) + ((mat & 1) << 3);
    int c16 = 2 * kk + (mat >> 1);
    return base + swz(row, c16);
}
__device__ __forceinline__ uint32_t addrB(uint32_t base, int n_base, int kk, int lane) {
    int l = lane & 15;
    int row = n_base + (l & 7);
    int c16 = 2 * kk + (l >> 3);
    return base + swz(row, c16);
}
__device__ __forceinline__ uint32_t addrBT(uint32_t base, int k_base, int n16, int lane) {
    int l = lane & 15;
    int row = k_base + (l & 7) + ((l >> 3) << 3);
    return base + swz(row, n16);
}

template <int R>
__device__ __forceinline__ void cp_tile(uint32_t dst, const bf16* src, int tid) {
    const int total = R * 8;
#pragma unroll
    for (int i = tid; i < total; i += 256) {
        int r = i >> 3, c = i & 7;
        cp16(dst + swz(r, c), src + (size_t)r * DM + c * 8);
    }
}

template <int R>
__device__ __forceinline__ void load_tile(char* dst, const bf16* src, int tid) {
    const int total = R * 8;
#pragma unroll
    for (int i = tid; i < total; i += 256) {
        int r = i >> 3, c = i & 7;
        uint4 v = *(const uint4*)(src + (size_t)r * DM + c * 8);
        *(uint4*)(dst + swz(r, c)) = v;
    }
}

__device__ __forceinline__ void split2(float x, float y, uint32_t& h, uint32_t& l) {
    __nv_bfloat162 hh = __floats2bfloat162_rn(x, y);
    __nv_bfloat162 ll = __floats2bfloat162_rn(x - __bfloat162float(hh.x),
                                              y - __bfloat162float(hh.y));
    h = *(uint32_t*)&hh;
    l = *(uint32_t*)&ll;
}
__device__ __forceinline__ void split2h(float x, float y, uint32_t& h, uint32_t& l) {
    __half2 hh = __floats2half2_rn(x, y);
    __half2 ll = __floats2half2_rn(x - __half2float(hh.x),
                                   y - __half2float(hh.y));
    h = *(uint32_t*)&hh;
    l = *(uint32_t*)&ll;
}

// ---------------------------------------------------------------------------
// fp32 -> bf16 hi/lo split conversion
// ---------------------------------------------------------------------------
__global__ void __launch_bounds__(256) conv_split(
    const float* __restrict__ x, bf16* __restrict__ h, bf16* __restrict__ l)
{
    size_t i = (size_t)(blockIdx.x * 256 + threadIdx.x) * 4;
    float4 v = *(const float4*)(x + i);
    uint32_t h01, l01, h23, l23;
    split2(v.x, v.y, h01, l01);
    split2(v.z, v.w, h23, l23);
    *(uint2*)(h + i) = make_uint2(h01, h23);
    *(uint2*)(l + i) = make_uint2(l01, l23);
}

// fp32 -> fp16 (hi only)
__global__ void __launch_bounds__(256) conv_h(
    const float* __restrict__ x, __half* __restrict__ h)
{
    size_t i = (size_t)(blockIdx.x * 256 + threadIdx.x) * 4;
    float4 v = *(const float4*)(x + i);
    __half2 a = __floats2half2_rn(v.x, v.y);
    __half2 b = __floats2half2_rn(v.z, v.w);
    *(uint2*)(h + i) = make_uint2(*(uint32_t*)&a, *(uint32_t*)&b);
}

// ---------------------------------------------------------------------------
// QKV projection GEMM (bf16 3-product): 2-stage cp.async pipeline.
// Tile 128x128, BK=64; 8 warps, warp tile 64x32.
// ofp16 != 0: output single fp16 (hi) into Ch.
// ---------------------------------------------------------------------------
__global__ void __launch_bounds__(256) proj_mma(
    const bf16* __restrict__ Xh, const bf16* __restrict__ Xl,
    const bf16* __restrict__ Wh, const bf16* __restrict__ Wl,
    const float* __restrict__ bias,
    bf16* __restrict__ Ch, bf16* __restrict__ Cl, int ofp16)
{
    extern __shared__ char dsm[];
    uint32_t sb0 = smem_u32(dsm);
    uint32_t sb = (sb0 + 127) & ~127u;

    const int tid = threadIdx.x, lane = tid & 31, wid = tid >> 5;
    const int wm = (wid & 1) << 6, wn = (wid >> 1) << 5;
    const int m0 = blockIdx.y << 7, n0 = blockIdx.x << 7;
    const int gid = lane >> 2, tig = lane & 3;

    const bf16* pXh = Xh + (size_t)m0 * DM;
    const bf16* pXl = Xl + (size_t)m0 * DM;
    const bf16* pWh = Wh + (size_t)n0 * DM;
    const bf16* pWl = Wl + (size_t)n0 * DM;

    float c[4][4][4];
#pragma unroll
    for (int i = 0; i < 4; i++)
#pragma unroll
        for (int j = 0; j < 4; j++)
#pragma unroll
            for (int k = 0; k < 4; k++) c[i][j][k] = 0.f;

    cp_tile<128>(sb,         pXh, tid);
    cp_tile<128>(sb + 16384, pXl, tid);
    cp_tile<128>(sb + 32768, pWh, tid);
    cp_tile<128>(sb + 49152, pWl, tid);
    cp_commit();

    for (int kt = 0; kt < 16; kt++) {
        const uint32_t st = sb + ((kt & 1) << 16);
        if (kt < 15) {
            const uint32_t nx = sb + (((kt + 1) & 1) << 16);
            const int ko = (kt + 1) * 64;
            cp_tile<128>(nx,         pXh + ko, tid);
            cp_tile<128>(nx + 16384, pXl + ko, tid);
            cp_tile<128>(nx + 32768, pWh + ko, tid);
            cp_tile<128>(nx + 49152, pWl + ko, tid);
            cp_commit();
            cp_wait<1>();
        } else {
            cp_wait<0>();
        }
        __syncthreads();
#pragma unroll
        for (int kk = 0; kk < 4; kk++) {
            uint32_t ah[4][4], al[4][4], bh[4][2], bl[4][2];
#pragma unroll
            for (int f = 0; f < 4; f++) {
                ldmA(ah[f], addrA(st,         wm + f * 16, kk, lane));
                ldmA(al[f], addrA(st + 16384, wm + f * 16, kk, lane));
                ldmB(bh[f], addrB(st + 32768, wn + f * 8,  kk, lane));
                ldmB(bl[f], addrB(st + 49152, wn + f * 8,  kk, lane));
            }
#pragma unroll
            for (int i = 0; i < 4; i++)
#pragma unroll
                for (int j = 0; j < 4; j++) {
                    mma16816(c[i][j], ah[i], bh[j]);
                    mma16816(c[i][j], al[i], bh[j]);
                    mma16816(c[i][j], ah[i], bl[j]);
                }
        }
        __syncthreads();
    }

#pragma unroll
    for (int i = 0; i < 4; i++) {
        int r0 = m0 + wm + i * 16 + gid, r1 = r0 + 8;
#pragma unroll
        for (int j = 0; j < 4; j++) {
            int col = n0 + wn + j * 8 + tig * 2;
            float2 bz = *(const float2*)(bias + col);
            float v00 = c[i][j][0] + bz.x, v01 = c[i][j][1] + bz.y;
            float v10 = c[i][j][2] + bz.x, v11 = c[i][j][3] + bz.y;
            if (ofp16) {
                __half2 a = __floats2half2_rn(v00, v01);
                __half2 b = __floats2half2_rn(v10, v11);
                *(uint32_t*)(Ch + (size_t)r0 * DM + col) = *(uint32_t*)&a;
                *(uint32_t*)(Ch + (size_t)r1 * DM + col) = *(uint32_t*)&b;
            } else {
                uint32_t h, l;
                split2(v00, v01, h, l);
                *(uint32_t*)(Ch + (size_t)r0 * DM + col) = h;
                *(uint32_t*)(Cl + (size_t)r0 * DM + col) = l;
                split2(v10, v11, h, l);
                *(uint32_t*)(Ch + (size_t)r1 * DM + col) = h;
                *(uint32_t*)(Cl + (size_t)r1 * DM + col) = l;
            }
        }
    }
}

// ---------------------------------------------------------------------------
// Output projection GEMM (fp16 2-product): g_o = (g_ch+g_cl) @ g_woh^T + bo.
// ---------------------------------------------------------------------------
__global__ void __launch_bounds__(256) projo_mma(const float* __restrict__ bias)
{
    extern __shared__ char dsm[];
    uint32_t sb0 = smem_u32(dsm);
    uint32_t sb = (sb0 + 127) & ~127u;

    const int tid = threadIdx.x, lane = tid & 31, wid = tid >> 5;
    const int wm = (wid & 1) << 6, wn = (wid >> 1) << 5;
    const int m0 = blockIdx.y << 7, n0 = blockIdx.x << 7;
    const int gid = lane >> 2, tig = lane & 3;

    const bf16* pXh = g_ch + (size_t)m0 * DM;
    const bf16* pXl = g_cl + (size_t)m0 * DM;
    const bf16* pWh = g_woh + (size_t)n0 * DM;

    float c[4][4][4];
#pragma unroll
    for (int i = 0; i < 4; i++)
#pragma unroll
        for (int j = 0; j < 4; j++)
#pragma unroll
            for (int k = 0; k < 4; k++) c[i][j][k] = 0.f;

    cp_tile<128>(sb,         pXh, tid);
    cp_tile<128>(sb + 16384, pXl, tid);
    cp_tile<128>(sb + 32768, pWh, tid);
    cp_commit();

    for (int kt = 0; kt < 16; kt++) {
        const uint32_t st = sb + (kt & 1) * 49152;
        if (kt < 15) {
            const uint32_t nx = sb + ((kt + 1) & 1) * 49152;
            const int ko = (kt + 1) * 64;
            cp_tile<128>(nx,         pXh + ko, tid);
            cp_tile<128>(nx + 16384, pXl + ko, tid);
            cp_tile<128>(nx + 32768, pWh + ko, tid);
            cp_commit();
            cp_wait<1>();
        } else {
            cp_wait<0>();
        }
        __syncthreads();
#pragma unroll
        for (int kk = 0; kk < 4; kk++) {
            uint32_t ah[4][4], al[4][4], bh[4][2];
#pragma unroll
            for (int f = 0; f < 4; f++) {
                ldmA(ah[f], addrA(st,         wm + f * 16, kk, lane));
                ldmA(al[f], addrA(st + 16384, wm + f * 16, kk, lane));
                ldmB(bh[f], addrB(st + 32768, wn + f * 8,  kk, lane));
            }
#pragma unroll
            for (int i = 0; i < 4; i++)
#pragma unroll
                for (int j = 0; j < 4; j++) {
                    mma16816h(c[i][j], ah[i], bh[j]);
                    mma16816h(c[i][j], al[i], bh[j]);
                }
        }
        __syncthreads();
    }

#pragma unroll
    for (int i = 0; i < 4; i++) {
        int r0 = m0 + wm + i * 16 + gid, r1 = r0 + 8;
#pragma unroll
        for (int j = 0; j < 4; j++) {
            int col = n0 + wn + j * 8 + tig * 2;
            float2 bz = *(const float2*)(bias + col);
            *(float2*)(g_o + (size_t)r0 * DM + col) =
                make_float2(c[i][j][0] + bz.x, c[i][j][1] + bz.y);
            *(float2*)(g_o + (size_t)r1 * DM + col) =
                make_float2(c[i][j][2] + bz.x, c[i][j][3] + bz.y);
        }
    }
}

// ---------------------------------------------------------------------------
// FUSED attention: score (bf16 3-product) + softmax bookkeeping + ctx
// (fp16, P-hi only) in one kernel. Grid (16 m-blocks, 64 bh), 256 threads.
//
// Per CTA (128-row q panel, one bh):
//   pass 1, 16 n-chunks of 128: score MMA -> mask/exp -> raw-e gmem write +
//     P staged to smem fp16 + rowsum(smem) -> ctx MMA accumulate (P @ V).
//     k/V chunks double-buffered with cp.async.
//   pass 2: rescale this panel's raw e (L2-hot) by 1/rowsum -> final attn.
//   ctx epilogue: scale by 1/rowsum, write fp16 hi/lo to g_ch/g_cl.
//
// SMEM: qH@0 qL@16K | k(s)@32K+32K*s (h@0,l@16K) | v(s)@96K+16K*s |
//       P@128K (two 64-col tiles) | srow@160K
// ---------------------------------------------------------------------------
__global__ void __launch_bounds__(256) fused_attn(
    const int* __restrict__ mask, float* __restrict__ EO)
{
    extern __shared__ char dsm[];
    uint32_t sb0 = smem_u32(dsm);
    uint32_t sb = (sb0 + 127) & ~127u;
    char* base = dsm + (sb - sb0);
    float* srow = (float*)(base + 163840);

    const int tid = threadIdx.x, lane = tid & 31, wid = tid >> 5;
    const int wm = (wid & 1) << 6, wn = (wid >> 1) << 5;   // score tile 64x32
    const int wnc = (wid >> 1) << 4;                        // ctx dk tile 64x16
    const int bh = blockIdx.y, bz = bh >> 4, h = bh & 15;
    const int m0 = blockIdx.x << 7;
    const int gid = lane >> 2, tig = lane & 3;

    if (tid < 128) srow[tid] = 0.f;

    const size_t hoff = (size_t)h * DK;
    const bf16* kbh = g_kh + (size_t)(bz * SQ) * DM + hoff;
    const bf16* kbl = g_kl + (size_t)(bz * SQ) * DM + hoff;
    const bf16* vb  = g_vh + (size_t)(bz * SQ) * DM + hoff;

    load_tile<128>(base,         g_qh + (size_t)(bz * SQ + m0) * DM + hoff, tid);
    load_tile<128>(base + 16384, g_ql + (size_t)(bz * SQ + m0) * DM + hoff, tid);

    // prefetch chunk 0
    cp_tile<128>(sb + 32768,         kbh, tid);
    cp_tile<128>(sb + 32768 + 16384, kbl, tid);
    cp_tile<128>(sb + 98304,         vb,  tid);
    cp_commit();

    float c2[4][2][4];
#pragma unroll
    for (int i = 0; i < 4; i++)
#pragma unroll
        for (int j = 0; j < 2; j++)
#pragma unroll
            for (int k = 0; k < 4; k++) c2[i][j][k] = 0.f;

    const int* mbase = mask + (size_t)bz * SQ * SQ;
    float* eo = EO + (size_t)bh * ABH;
    const float scale = 0.125f;

    for (int t = 0; t < 16; t++) {
        const int s = t & 1;
        const uint32_t kS = sb + 32768 + s * 32768;
        const uint32_t vS = sb + 98304 + s * 16384;

        __syncthreads();   // prev ctx done: other k/v stage + P free
        if (t < 15) {
            const int s1 = s ^ 1;
            const bf16* ksrc = kbh + (size_t)(t + 1) * 128 * DM;
            const bf16* lsrc = kbl + (size_t)(t + 1) * 128 * DM;
            const bf16* vsrc = vb  + (size_t)(t + 1) * 128 * DM;
            cp_tile<128>(sb + 32768 + s1 * 32768,         ksrc, tid);
            cp_tile<128>(sb + 32768 + s1 * 32768 + 16384, lsrc, tid);
            cp_tile<128>(sb + 98304 + s1 * 16384,         vsrc, tid);
            cp_commit();
            cp_wait<1>();
        } else {
            cp_wait<0>();
        }
        __syncthreads();   // stage t tiles visible

        // ---- score: q(128x64) @ k_chunk(128x64)^T, bf16 3-product ----
        float c[4][4][4];
#pragma unroll
        for (int i = 0; i < 4; i++)
#pragma unroll
            for (int j = 0; j < 4; j++)
#pragma unroll
                for (int k = 0; k < 4; k++) c[i][j][k] = 0.f;

#pragma unroll
        for (int kk = 0; kk < 4; kk++) {
            uint32_t ah[4][4], al[4][4], bh2[4][2], bl2[4][2];
#pragma unroll
            for (int f = 0; f < 4; f++) {
                ldmA(ah[f], addrA(sb,         wm + f * 16, kk, lane));
                ldmA(al[f], addrA(sb + 16384, wm + f * 16, kk, lane));
                ldmB(bh2[f], addrB(kS,         wn + f * 8, kk, lane));
                ldmB(bl2[f], addrB(kS + 16384, wn + f * 8, kk, lane));
            }
#pragma unroll
            for (int i = 0; i < 4; i++)
#pragma unroll
                for (int j = 0; j < 4; j++) {
                    mma16816(c[i][j], ah[i], bh2[j]);
                    mma16816(c[i][j], al[i], bh2[j]);
                    mma16816(c[i][j], ah[i], bl2[j]);
                }
        }

        // ---- epilogue: mask+exp, raw-e write, rowsum, stage P (fp16 hi) ----
        const int n0c = t << 7;
#pragma unroll
        for (int i = 0; i < 4; i++) {
            int lr0 = wm + i * 16 + gid, lr1 = lr0 + 8;
            int r0 = m0 + lr0, r1 = m0 + lr1;
            float rs0 = 0.f, rs1 = 0.f;
#pragma unroll
            for (int j = 0; j < 4; j++) {
                int col = wn + j * 8 + tig * 2;        // local n 0..127
                int gcol = n0c + col;
                int2 mv0 = *(const int2*)(mbase + (size_t)r0 * SQ + gcol);
                int2 mv1 = *(const int2*)(mbase + (size_t)r1 * SQ + gcol);
                float e00 = mv0.x ? __expf(c[i][j][0] * scale) : 0.f;
                float e01 = mv0.y ? __expf(c[i][j][1] * scale) : 0.f;
                float e10 = mv1.x ? __expf(c[i][j][2] * scale) : 0.f;
                float e11 = mv1.y ? __expf(c[i][j][3] * scale) : 0.f;
                *(float2*)(eo + (size_t)r0 * SQ + gcol) = make_float2(e00, e01);
                *(float2*)(eo + (size_t)r1 * SQ + gcol) = make_float2(e10, e11);
                rs0 += e00 + e01;
                rs1 += e10 + e11;
                // stage P hi (fp16): tile = col>>6, within-tile col cc
                int cc = col & 63;
                uint32_t tb = sb + 131072 + ((uint32_t)(col >> 6) << 14);
                uint32_t a0 = tb + swz(lr0, cc >> 3) + (cc & 7) * 2;
                uint32_t a1 = tb + swz(lr1, cc >> 3) + (cc & 7) * 2;
                __half2 p0 = __floats2half2_rn(e00, e01);
                __half2 p1 = __floats2half2_rn(e10, e11);
                *(uint32_t*)(base + (a0 - sb)) = *(uint32_t*)&p0;
                *(uint32_t*)(base + (a1 - sb)) = *(uint32_t*)&p1;
            }
            rs0 += __shfl_xor_sync(0xffffffffu, rs0, 1);
            rs0 += __shfl_xor_sync(0xffffffffu, rs0, 2);
            rs1 += __shfl_xor_sync(0xffffffffu, rs1, 1);
            rs1 += __shfl_xor_sync(0xffffffffu, rs1, 2);
            if (tig == 0) {
                atomicAdd(&srow[lr0], rs0);
                atomicAdd(&srow[lr1], rs1);
            }
        }
        __syncthreads();   // P visible to all warps

        // ---- ctx accumulate: P(128x128 fp16) @ v_chunk(128x64 fp16) ----
#pragma unroll
        for (int kkc = 0; kkc < 8; kkc++) {
            const uint32_t pt = sb + 131072 + ((uint32_t)(kkc >> 2) << 14);
            uint32_t ap[4][4], b2[2][2];
#pragma unroll
            for (int f = 0; f < 4; f++)
                ldmA(ap[f], addrA(pt, wm + f * 16, kkc & 3, lane));
#pragma unroll
            for (int f = 0; f < 2; f++)
                ldmBT(b2[f], addrBT(vS, kkc * 16, (wnc >> 3) + f, lane));
#pragma unroll
            for (int i = 0; i < 4; i++)
#pragma unroll
                for (int j = 0; j < 2; j++)
                    mma16816h(c2[i][j], ap[i], b2[j]);
        }
    }

    __syncthreads();
    if (tid < 128) srow[tid] = 1.0f / srow[tid];
    __syncthreads();

    // ---- ctx epilogue: scale by rinv, fp16 hi/lo to g_ch/g_cl ----
#pragma unroll
    for (int i = 0; i < 4; i++) {
        int lr0 = wm + i * 16 + gid;
        float ri0 = srow[lr0], ri1 = srow[lr0 + 8];
        int r0 = bz * SQ + m0 + lr0, r1 = r0 + 8;
#pragma unroll
        for (int j = 0; j < 2; j++) {
            int col = h * DK + wnc + j * 8 + tig * 2;
            uint32_t hh, ll;
            split2h(c2[i][j][0] * ri0, c2[i][j][1] * ri0, hh, ll);
            *(uint32_t*)(g_ch + (size_t)r0 * DM + col) = hh;
            *(uint32_t*)(g_cl + (size_t)r0 * DM + col) = ll;
            split2h(c2[i][j][2] * ri1, c2[i][j][3] * ri1, hh, ll);
            *(uint32_t*)(g_ch + (size_t)r1 * DM + col) = hh;
            *(uint32_t*)(g_cl + (size_t)r1 * DM + col) = ll;
        }
    }

    // ---- pass 2: normalize this panel's raw e (L2-hot) ----
    for (int idx = tid; idx < 128 * 512; idx += 256) {
        int r = idx >> 9, c4 = idx & 511;
        float ri = srow[r];
        float4* p = (float4*)(eo + (size_t)(m0 + r) * SQ + c4 * 4);
        float4 e = *p;
        *p = make_float4(e.x * ri, e.y * ri, e.z * ri, e.w * ri);
    }
}

// ---------------------------------------------------------------------------
// Residual + LayerNorm: y = LN(g_o + Q) * gamma + beta
// ---------------------------------------------------------------------------
__global__ void __launch_bounds__(256) ln_kernel(
    const float* __restrict__ Qin, const float* __restrict__ gam,
    const float* __restrict__ bet, float* __restrict__ Y)
{
    __shared__ float red[16];
    const int row = blockIdx.x;
    const int tid = threadIdx.x;
    const float* op = g_o + (size_t)row * DM;
    const float* qp = Qin + (size_t)row * DM;

    float4 o4 = *(const float4*)(op + tid * 4);
    float4 q4 = *(const float4*)(qp + tid * 4);
    float x0 = o4.x + q4.x;
    float x1 = o4.y + q4.y;
    float x2 = o4.z + q4.z;
    float x3 = o4.w + q4.w;
    float s  = x0 + x1 + x2 + x3;
    float s2 = x0 * x0 + x1 * x1 + x2 * x2 + x3 * x3;

#pragma unroll
    for (int off = 16; off > 0; off >>= 1) {
        s  += __shfl_xor_sync(0xffffffffu, s,  off);
        s2 += __shfl_xor_sync(0xffffffffu, s2, off);
    }
    int warp = tid >> 5, lane = tid & 31;
    if (lane == 0) { red[warp] = s; red[8 + warp] = s2; }
    __syncthreads();
    if (tid == 0) {
        float ts = 0.f, ts2 = 0.f;
#pragma unroll
        for (int w = 0; w < 8; w++) { ts += red[w]; ts2 += red[8 + w]; }
        red[0] = ts; red[8] = ts2;
    }
    __syncthreads();
    float mu  = red[0] * (1.0f / DM);
    float var = red[8] * (1.0f / DM) - mu * mu;
    float rstd = rsqrtf(var + 1e-5f);

    float4 g4 = *(const float4*)(gam + tid * 4);
    float4 b4 = *(const float4*)(bet + tid * 4);
    float4 y4;
    y4.x = (x0 - mu) * rstd * g4.x + b4.x;
    y4.y = (x1 - mu) * rstd * g4.y + b4.y;
    y4.z = (x2 - mu) * rstd * g4.z + b4.z;
    y4.w = (x3 - mu) * rstd * g4.w + b4.w;
    *(float4*)(Y + (size_t)row * DM + tid * 4) = y4;
}

// ---------------------------------------------------------------------------
extern "C" void kernel_launch(void* const* d_in, const int* in_sizes, int n_in,
                              void* d_out, int out_size)
{
    (void)in_sizes; (void)n_in; (void)out_size;
    const float* Q    = (const float*)d_in[0];
    const float* K    = (const float*)d_in[1];
    const float* V    = (const float*)d_in[2];
    const int*   mask = (const int*)  d_in[3];
    const float* Wq   = (const float*)d_in[4];
    const float* bq   = (const float*)d_in[5];
    const float* Wk   = (const float*)d_in[6];
    const float* bk   = (const float*)d_in[7];
    const float* Wv   = (const float*)d_in[8];
    const float* bv   = (const float*)d_in[9];
    const float* Wo   = (const float*)d_in[10];
    const float* bo   = (const float*)d_in[11];
    const float* lg   = (const float*)d_in[12];
    const float* lb   = (const float*)d_in[13];

    float* y    = (float*)d_out;
    float* attn = y + YSZ;

    bf16 *xh, *xl, *x2h, *x2l, *x3h, *x3l;
    bf16 *wh, *wl, *w2h, *w2l, *w3h, *w3l, *woh;
    bf16 *qh, *ql, *kh, *kl, *vh;
    cudaGetSymbolAddress((void**)&xh,  g_xh);
    cudaGetSymbolAddress((void**)&xl,  g_xl);
    cudaGetSymbolAddress((void**)&x2h, g_x2h);
    cudaGetSymbolAddress((void**)&x2l, g_x2l);
    cudaGetSymbolAddress((void**)&x3h, g_x3h);
    cudaGetSymbolAddress((void**)&x3l, g_x3l);
    cudaGetSymbolAddress((void**)&wh,  g_wh);
    cudaGetSymbolAddress((void**)&wl,  g_wl);
    cudaGetSymbolAddress((void**)&w2h, g_w2h);
    cudaGetSymbolAddress((void**)&w2l, g_w2l);
    cudaGetSymbolAddress((void**)&w3h, g_w3h);
    cudaGetSymbolAddress((void**)&w3l, g_w3l);
    cudaGetSymbolAddress((void**)&woh, g_woh);
    cudaGetSymbolAddress((void**)&qh,  g_qh);
    cudaGetSymbolAddress((void**)&ql,  g_ql);
    cudaGetSymbolAddress((void**)&kh,  g_kh);
    cudaGetSymbolAddress((void**)&kl,  g_kl);
    cudaGetSymbolAddress((void**)&vh,  g_vh);

    const int SM_PROJ  = 131072 + 128;
    const int SM_PROJO = 98304 + 128;
    const int SM_FUSED = 164352 + 128;
    cudaFuncSetAttribute(proj_mma,   cudaFuncAttributeMaxDynamicSharedMemorySize, SM_PROJ);
    cudaFuncSetAttribute(projo_mma,  cudaFuncAttributeMaxDynamicSharedMemorySize, SM_PROJO);
    cudaFuncSetAttribute(fused_attn, cudaFuncAttributeMaxDynamicSharedMemorySize, SM_FUSED);

    const int gx = (MROWS * DM / 4) / 256;
    const int gw = (DM * DM / 4) / 256;
    dim3 gp(DM / 128, MROWS / 128);          // (8, 64)

    conv_split<<<gw, 256>>>(Wq, wh,  wl);
    conv_split<<<gx, 256>>>(Q,  xh,  xl);
    conv_split<<<gw, 256>>>(Wk, w2h, w2l);
    conv_split<<<gx, 256>>>(K,  x2h, x2l);
    conv_split<<<gw, 256>>>(Wv, w3h, w3l);
    proj_mma<<<gp, 256, SM_PROJ>>>(xh, xl, wh, wl, bq, qh, ql, 0);
    conv_split<<<gx, 256>>>(V,  x3h, x3l);
    conv_h<<<gw, 256>>>(Wo, (__half*)woh);
    proj_mma<<<gp, 256, SM_PROJ>>>(x2h, x2l, w2h, w2l, bk, kh, kl, 0);
    proj_mma<<<gp, 256, SM_PROJ>>>(x3h, x3l, w3h, w3l, bv, vh, nullptr, 1);

    dim3 gf(SQ / 128, NB * NH);              // (16, 64)
    fused_attn<<<gf, 256, SM_FUSED>>>(mask, attn);

    projo_mma<<<gp, 256, SM_PROJO>>>(bo);

    ln_kernel<<<MROWS, 256>>>(Q, lg, lb, y);
}

// round 15
// speedup vs baseline: 1.1861x; 1.1861x over previous
#include <cuda_runtime.h>
#include <cuda_bf16.h>
#include <cuda_fp16.h>
#include <stdint.h>

#define DM 1024
#define NH 16
#define DK 64
#define NB 4
#define SQ 2048
#define MROWS (NB * SQ)                 // 8192
#define YSZ ((size_t)MROWS * DM)
#define ABH ((size_t)SQ * SQ)

typedef __nv_bfloat16 bf16;

// ---------------------------------------------------------------------------
// Scratch (allocation-free rule: __device__ globals). 16-bit buffers are
// dtype-agnostic byte storage (bf16 or fp16 depending on stage).
// ---------------------------------------------------------------------------
__device__ bf16 g_xh[MROWS * DM],  g_xl[MROWS * DM];    // Q input (bf16 hi/lo)
__device__ bf16 g_x2h[MROWS * DM], g_x2l[MROWS * DM];   // K input
__device__ bf16 g_x3h[MROWS * DM], g_x3l[MROWS * DM];   // V input
__device__ bf16 g_ch[MROWS * DM],  g_cl[MROWS * DM];    // ctx output (fp16 hi/lo)
__device__ bf16 g_wh[DM * DM],  g_wl[DM * DM];          // Wq (bf16 hi/lo)
__device__ bf16 g_w2h[DM * DM], g_w2l[DM * DM];         // Wk
__device__ bf16 g_w3h[DM * DM], g_w3l[DM * DM];         // Wv
__device__ bf16 g_woh[DM * DM];                         // Wo (fp16 hi)
__device__ bf16 g_qh[MROWS * DM], g_ql[MROWS * DM];     // q (bf16 hi/lo)
__device__ bf16 g_kh[MROWS * DM], g_kl[MROWS * DM];     // k (bf16 hi/lo)
__device__ bf16 g_vh[MROWS * DM];                       // v (fp16 hi only)
__device__ __half g_e[(size_t)NB * NH * SQ * SQ];       // raw e, fp16 (536MB)
__device__ float g_o[MROWS * DM];
__device__ float g_rsum[NB * NH * SQ];

// ---------------------------------------------------------------------------
// Baseline-PTX helpers (sm_80-era: legal on plain compute_103)
// ---------------------------------------------------------------------------
__device__ __forceinline__ uint32_t smem_u32(const void* p) {
    uint32_t a;
    asm("{ .reg .u64 t; cvta.to.shared.u64 t, %1; cvt.u32.u64 %0, t; }"
        : "=r"(a) : "l"(p));
    return a;
}

__device__ __forceinline__ void mma16816(float* c, const uint32_t* a, const uint32_t* b) {
    asm volatile(
        "mma.sync.aligned.m16n8k16.row.col.f32.bf16.bf16.f32 "
        "{%0,%1,%2,%3}, {%4,%5,%6,%7}, {%8,%9}, {%0,%1,%2,%3};"
        : "+f"(c[0]), "+f"(c[1]), "+f"(c[2]), "+f"(c[3])
        : "r"(a[0]), "r"(a[1]), "r"(a[2]), "r"(a[3]), "r"(b[0]), "r"(b[1]));
}
__device__ __forceinline__ void mma16816h(float* c, const uint32_t* a, const uint32_t* b) {
    asm volatile(
        "mma.sync.aligned.m16n8k16.row.col.f32.f16.f16.f32 "
        "{%0,%1,%2,%3}, {%4,%5,%6,%7}, {%8,%9}, {%0,%1,%2,%3};"
        : "+f"(c[0]), "+f"(c[1]), "+f"(c[2]), "+f"(c[3])
        : "r"(a[0]), "r"(a[1]), "r"(a[2]), "r"(a[3]), "r"(b[0]), "r"(b[1]));
}

__device__ __forceinline__ void ldmA(uint32_t* r, uint32_t addr) {
    asm volatile("ldmatrix.sync.aligned.m8n8.x4.shared.b16 {%0,%1,%2,%3}, [%4];"
        : "=r"(r[0]), "=r"(r[1]), "=r"(r[2]), "=r"(r[3]) : "r"(addr));
}
__device__ __forceinline__ void ldmB(uint32_t* r, uint32_t addr) {
    asm volatile("ldmatrix.sync.aligned.m8n8.x2.shared.b16 {%0,%1}, [%2];"
        : "=r"(r[0]), "=r"(r[1]) : "r"(addr));
}
__device__ __forceinline__ void ldmBT(uint32_t* r, uint32_t addr) {
    asm volatile("ldmatrix.sync.aligned.m8n8.x2.trans.shared.b16 {%0,%1}, [%2];"
        : "=r"(r[0]), "=r"(r[1]) : "r"(addr));
}

__device__ __forceinline__ void cp16(uint32_t dst, const void* src) {
    asm volatile("cp.async.cg.shared.global [%0], [%1], 16;" :: "r"(dst), "l"(src));
}
__device__ __forceinline__ void cp_commit() {
    asm volatile("cp.async.commit_group;" ::: "memory");
}
template <int N>
__device__ __forceinline__ void cp_wait() {
    asm volatile("cp.async.wait_group %0;" :: "n"(N) : "memory");
}

// Tile rows are 64 halfwords = 128B, XOR-swizzled in 16B granules.
__device__ __forceinline__ uint32_t swz(int row, int c16) {
    return (uint32_t)(row * 128 + ((c16 ^ (row & 7)) << 4));
}
__device__ __forceinline__ uint32_t addrA(uint32_t base, int m_base, int kk, int lane) {
    int mat = lane >> 3;
    int row = m_base + (lane & 7) + ((mat & 1) << 3);
    int c16 = 2 * kk + (mat >> 1);
    return base + swz(row, c16);
}
__device__ __forceinline__ uint32_t addrB(uint32_t base, int n_base, int kk, int lane) {
    int l = lane & 15;
    int row = n_base + (l & 7);
    int c16 = 2 * kk + (l >> 3);
    return base + swz(row, c16);
}
__device__ __forceinline__ uint32_t addrBT(uint32_t base, int k_base, int n16, int lane) {
    int l = lane & 15;
    int row = k_base + (l & 7) + ((l >> 3) << 3);
    return base + swz(row, n16);
}

template <int R>
__device__ __forceinline__ void cp_tile(uint32_t dst, const bf16* src, int tid) {
    const int total = R * 8;
#pragma unroll
    for (int i = tid; i < total; i += 256) {
        int r = i >> 3, c = i & 7;
        cp16(dst + swz(r, c), src + (size_t)r * DM + c * 8);
    }
}

template <int R>
__device__ __forceinline__ void load_tile(char* dst, const bf16* src, int tid) {
    const int total = R * 8;
#pragma unroll
    for (int i = tid; i < total; i += 256) {
        int r = i >> 3, c = i & 7;
        uint4 v = *(const uint4*)(src + (size_t)r * DM + c * 8);
        *(uint4*)(dst + swz(r, c)) = v;
    }
}

__device__ __forceinline__ void split2(float x, float y, uint32_t& h, uint32_t& l) {
    __nv_bfloat162 hh = __floats2bfloat162_rn(x, y);
    __nv_bfloat162 ll = __floats2bfloat162_rn(x - __bfloat162float(hh.x),
                                              y - __bfloat162float(hh.y));
    h = *(uint32_t*)&hh;
    l = *(uint32_t*)&ll;
}
__device__ __forceinline__ void split2h(float x, float y, uint32_t& h, uint32_t& l) {
    __half2 hh = __floats2half2_rn(x, y);
    __half2 ll = __floats2half2_rn(x - __half2float(hh.x),
                                   y - __half2float(hh.y));
    h = *(uint32_t*)&hh;
    l = *(uint32_t*)&ll;
}

// ---------------------------------------------------------------------------
// fp32 -> bf16 hi/lo split conversion
// ---------------------------------------------------------------------------
__global__ void __launch_bounds__(256) conv_split(
    const float* __restrict__ x, bf16* __restrict__ h, bf16* __restrict__ l)
{
    size_t i = (size_t)(blockIdx.x * 256 + threadIdx.x) * 4;
    float4 v = *(const float4*)(x + i);
    uint32_t h01, l01, h23, l23;
    split2(v.x, v.y, h01, l01);
    split2(v.z, v.w, h23, l23);
    *(uint2*)(h + i) = make_uint2(h01, h23);
    *(uint2*)(l + i) = make_uint2(l01, l23);
}

// fp32 -> fp16 (hi only)
__global__ void __launch_bounds__(256) conv_h(
    const float* __restrict__ x, __half* __restrict__ h)
{
    size_t i = (size_t)(blockIdx.x * 256 + threadIdx.x) * 4;
    float4 v = *(const float4*)(x + i);
    __half2 a = __floats2half2_rn(v.x, v.y);
    __half2 b = __floats2half2_rn(v.z, v.w);
    *(uint2*)(h + i) = make_uint2(*(uint32_t*)&a, *(uint32_t*)&b);
}

// ---------------------------------------------------------------------------
// QKV projection GEMM (bf16 3-product): 2-stage cp.async pipeline.
// Tile 128x128, BK=64; 8 warps, warp tile 64x32.
// ofp16 != 0: output single fp16 (hi) into Ch.
// ---------------------------------------------------------------------------
__global__ void __launch_bounds__(256) proj_mma(
    const bf16* __restrict__ Xh, const bf16* __restrict__ Xl,
    const bf16* __restrict__ Wh, const bf16* __restrict__ Wl,
    const float* __restrict__ bias,
    bf16* __restrict__ Ch, bf16* __restrict__ Cl, int ofp16)
{
    extern __shared__ char dsm[];
    uint32_t sb0 = smem_u32(dsm);
    uint32_t sb = (sb0 + 127) & ~127u;

    const int tid = threadIdx.x, lane = tid & 31, wid = tid >> 5;
    const int wm = (wid & 1) << 6, wn = (wid >> 1) << 5;
    const int m0 = blockIdx.y << 7, n0 = blockIdx.x << 7;
    const int gid = lane >> 2, tig = lane & 3;

    const bf16* pXh = Xh + (size_t)m0 * DM;
    const bf16* pXl = Xl + (size_t)m0 * DM;
    const bf16* pWh = Wh + (size_t)n0 * DM;
    const bf16* pWl = Wl + (size_t)n0 * DM;

    float c[4][4][4];
#pragma unroll
    for (int i = 0; i < 4; i++)
#pragma unroll
        for (int j = 0; j < 4; j++)
#pragma unroll
            for (int k = 0; k < 4; k++) c[i][j][k] = 0.f;

    cp_tile<128>(sb,         pXh, tid);
    cp_tile<128>(sb + 16384, pXl, tid);
    cp_tile<128>(sb + 32768, pWh, tid);
    cp_tile<128>(sb + 49152, pWl, tid);
    cp_commit();

    for (int kt = 0; kt < 16; kt++) {
        const uint32_t st = sb + ((kt & 1) << 16);
        if (kt < 15) {
            const uint32_t nx = sb + (((kt + 1) & 1) << 16);
            const int ko = (kt + 1) * 64;
            cp_tile<128>(nx,         pXh + ko, tid);
            cp_tile<128>(nx + 16384, pXl + ko, tid);
            cp_tile<128>(nx + 32768, pWh + ko, tid);
            cp_tile<128>(nx + 49152, pWl + ko, tid);
            cp_commit();
            cp_wait<1>();
        } else {
            cp_wait<0>();
        }
        __syncthreads();
#pragma unroll
        for (int kk = 0; kk < 4; kk++) {
            uint32_t ah[4][4], al[4][4], bh[4][2], bl[4][2];
#pragma unroll
            for (int f = 0; f < 4; f++) {
                ldmA(ah[f], addrA(st,         wm + f * 16, kk, lane));
                ldmA(al[f], addrA(st + 16384, wm + f * 16, kk, lane));
                ldmB(bh[f], addrB(st + 32768, wn + f * 8,  kk, lane));
                ldmB(bl[f], addrB(st + 49152, wn + f * 8,  kk, lane));
            }
#pragma unroll
            for (int i = 0; i < 4; i++)
#pragma unroll
                for (int j = 0; j < 4; j++) {
                    mma16816(c[i][j], ah[i], bh[j]);
                    mma16816(c[i][j], al[i], bh[j]);
                    mma16816(c[i][j], ah[i], bl[j]);
                }
        }
        __syncthreads();
    }

#pragma unroll
    for (int i = 0; i < 4; i++) {
        int r0 = m0 + wm + i * 16 + gid, r1 = r0 + 8;
#pragma unroll
        for (int j = 0; j < 4; j++) {
            int col = n0 + wn + j * 8 + tig * 2;
            float2 bz = *(const float2*)(bias + col);
            float v00 = c[i][j][0] + bz.x, v01 = c[i][j][1] + bz.y;
            float v10 = c[i][j][2] + bz.x, v11 = c[i][j][3] + bz.y;
            if (ofp16) {
                __half2 a = __floats2half2_rn(v00, v01);
                __half2 b = __floats2half2_rn(v10, v11);
                *(uint32_t*)(Ch + (size_t)r0 * DM + col) = *(uint32_t*)&a;
                *(uint32_t*)(Ch + (size_t)r1 * DM + col) = *(uint32_t*)&b;
            } else {
                uint32_t h, l;
                split2(v00, v01, h, l);
                *(uint32_t*)(Ch + (size_t)r0 * DM + col) = h;
                *(uint32_t*)(Cl + (size_t)r0 * DM + col) = l;
                split2(v10, v11, h, l);
                *(uint32_t*)(Ch + (size_t)r1 * DM + col) = h;
                *(uint32_t*)(Cl + (size_t)r1 * DM + col) = l;
            }
        }
    }
}

// ---------------------------------------------------------------------------
// Output projection GEMM (fp16 2-product): g_o = (g_ch+g_cl) @ g_woh^T + bo.
// ---------------------------------------------------------------------------
__global__ void __launch_bounds__(256) projo_mma(const float* __restrict__ bias)
{
    extern __shared__ char dsm[];
    uint32_t sb0 = smem_u32(dsm);
    uint32_t sb = (sb0 + 127) & ~127u;

    const int tid = threadIdx.x, lane = tid & 31, wid = tid >> 5;
    const int wm = (wid & 1) << 6, wn = (wid >> 1) << 5;
    const int m0 = blockIdx.y << 7, n0 = blockIdx.x << 7;
    const int gid = lane >> 2, tig = lane & 3;

    const bf16* pXh = g_ch + (size_t)m0 * DM;
    const bf16* pXl = g_cl + (size_t)m0 * DM;
    const bf16* pWh = g_woh + (size_t)n0 * DM;

    float c[4][4][4];
#pragma unroll
    for (int i = 0; i < 4; i++)
#pragma unroll
        for (int j = 0; j < 4; j++)
#pragma unroll
            for (int k = 0; k < 4; k++) c[i][j][k] = 0.f;

    cp_tile<128>(sb,         pXh, tid);
    cp_tile<128>(sb + 16384, pXl, tid);
    cp_tile<128>(sb + 32768, pWh, tid);
    cp_commit();

    for (int kt = 0; kt < 16; kt++) {
        const uint32_t st = sb + (kt & 1) * 49152;
        if (kt < 15) {
            const uint32_t nx = sb + ((kt + 1) & 1) * 49152;
            const int ko = (kt + 1) * 64;
            cp_tile<128>(nx,         pXh + ko, tid);
            cp_tile<128>(nx + 16384, pXl + ko, tid);
            cp_tile<128>(nx + 32768, pWh + ko, tid);
            cp_commit();
            cp_wait<1>();
        } else {
            cp_wait<0>();
        }
        __syncthreads();
#pragma unroll
        for (int kk = 0; kk < 4; kk++) {
            uint32_t ah[4][4], al[4][4], bh[4][2];
#pragma unroll
            for (int f = 0; f < 4; f++) {
                ldmA(ah[f], addrA(st,         wm + f * 16, kk, lane));
                ldmA(al[f], addrA(st + 16384, wm + f * 16, kk, lane));
                ldmB(bh[f], addrB(st + 32768, wn + f * 8,  kk, lane));
            }
#pragma unroll
            for (int i = 0; i < 4; i++)
#pragma unroll
                for (int j = 0; j < 4; j++) {
                    mma16816h(c[i][j], ah[i], bh[j]);
                    mma16816h(c[i][j], al[i], bh[j]);
                }
        }
        __syncthreads();
    }

#pragma unroll
    for (int i = 0; i < 4; i++) {
        int r0 = m0 + wm + i * 16 + gid, r1 = r0 + 8;
#pragma unroll
        for (int j = 0; j < 4; j++) {
            int col = n0 + wn + j * 8 + tig * 2;
            float2 bz = *(const float2*)(bias + col);
            *(float2*)(g_o + (size_t)r0 * DM + col) =
                make_float2(c[i][j][0] + bz.x, c[i][j][1] + bz.y);
            *(float2*)(g_o + (size_t)r1 * DM + col) =
                make_float2(c[i][j][2] + bz.x, c[i][j][3] + bz.y);
        }
    }
}

// ---------------------------------------------------------------------------
// Score GEMM + mask/exp epilogue + row sums (bf16 3-product, K=64).
// Writes raw e as fp16 into g_e; rowsums (fp32-exact) into g_rsum.
// ---------------------------------------------------------------------------
__global__ void __launch_bounds__(256) score_mma(const int* __restrict__ mask)
{
    extern __shared__ char dsm[];
    uint32_t sb0 = smem_u32(dsm);
    uint32_t sb = (sb0 + 127) & ~127u;
    char* base = dsm + (sb - sb0);
    float* srow = (float*)(base + 65536);

    const int tid = threadIdx.x, lane = tid & 31, wid = tid >> 5;
    const int wm = (wid & 1) << 6, wn = (wid >> 1) << 5;
    const int bh = blockIdx.z, bz = bh >> 4, h = bh & 15;
    const int m0 = blockIdx.y << 7, n0 = blockIdx.x << 7;
    const int gid = lane >> 2, tig = lane & 3;

    if (tid < 128) srow[tid] = 0.f;

    const size_t qrow = (size_t)(bz * SQ + m0) * DM + h * DK;
    const size_t krow = (size_t)(bz * SQ + n0) * DM + h * DK;
    load_tile<128>(base,         g_qh + qrow, tid);
    load_tile<128>(base + 16384, g_ql + qrow, tid);
    load_tile<128>(base + 32768, g_kh + krow, tid);
    load_tile<128>(base + 49152, g_kl + krow, tid);
    __syncthreads();

    float c[4][4][4];
#pragma unroll
    for (int i = 0; i < 4; i++)
#pragma unroll
        for (int j = 0; j < 4; j++)
#pragma unroll
            for (int k = 0; k < 4; k++) c[i][j][k] = 0.f;

#pragma unroll
    for (int kk = 0; kk < 4; kk++) {
        uint32_t ah[4][4], al[4][4], bh2[4][2], bl2[4][2];
#pragma unroll
        for (int f = 0; f < 4; f++) {
            ldmA(ah[f], addrA(sb,         wm + f * 16, kk, lane));
            ldmA(al[f], addrA(sb + 16384, wm + f * 16, kk, lane));
            ldmB(bh2[f], addrB(sb + 32768, wn + f * 8, kk, lane));
            ldmB(bl2[f], addrB(sb + 49152, wn + f * 8, kk, lane));
        }
#pragma unroll
        for (int i = 0; i < 4; i++)
#pragma unroll
            for (int j = 0; j < 4; j++) {
                mma16816(c[i][j], ah[i], bh2[j]);
                mma16816(c[i][j], al[i], bh2[j]);
                mma16816(c[i][j], ah[i], bl2[j]);
            }
    }

    const int* mbase = mask + (size_t)bz * SQ * SQ;
    __half* ge = g_e + (size_t)bh * ABH;
    const float scale = 0.125f;

#pragma unroll
    for (int i = 0; i < 4; i++) {
        int r0 = m0 + wm + i * 16 + gid, r1 = r0 + 8;
        float rs0 = 0.f, rs1 = 0.f;
#pragma unroll
        for (int j = 0; j < 4; j++) {
            int col = n0 + wn + j * 8 + tig * 2;
            int2 mv0 = *(const int2*)(mbase + (size_t)r0 * SQ + col);
            int2 mv1 = *(const int2*)(mbase + (size_t)r1 * SQ + col);
            float e00 = mv0.x ? __expf(c[i][j][0] * scale) : 0.f;
            float e01 = mv0.y ? __expf(c[i][j][1] * scale) : 0.f;
            float e10 = mv1.x ? __expf(c[i][j][2] * scale) : 0.f;
            float e11 = mv1.y ? __expf(c[i][j][3] * scale) : 0.f;
            __half2 p0 = __floats2half2_rn(e00, e01);
            __half2 p1 = __floats2half2_rn(e10, e11);
            *(__half2*)(ge + (size_t)r0 * SQ + col) = p0;
            *(__half2*)(ge + (size_t)r1 * SQ + col) = p1;
            rs0 += e00 + e01;
            rs1 += e10 + e11;
        }
        rs0 += __shfl_xor_sync(0xffffffffu, rs0, 1);
        rs0 += __shfl_xor_sync(0xffffffffu, rs0, 2);
        rs1 += __shfl_xor_sync(0xffffffffu, rs1, 1);
        rs1 += __shfl_xor_sync(0xffffffffu, rs1, 2);
        if (tig == 0) {
            atomicAdd(&srow[wm + i * 16 + gid],     rs0);
            atomicAdd(&srow[wm + i * 16 + gid + 8], rs1);
        }
    }
    __syncthreads();
    if (tid < 128)
        atomicAdd(&g_rsum[(size_t)bh * SQ + m0 + tid], srow[tid]);
}

// ---------------------------------------------------------------------------
// Context GEMM (fp16 1-product): ctx = rinv * (E16 @ V16).
// cp.async streams fp16 e DIRECTLY into MMA-ready swizzled P tiles (no
// conversion pass). Writes normalized fp32 attn from smem. SMEM ~50KB ->
// 4 CTAs/SM.  Layout: P(s)@s*16K | V(s)@32K+8K*s | rv@48K
// ---------------------------------------------------------------------------
__global__ void __launch_bounds__(256) ctx_mma(float* __restrict__ EO)
{
    extern __shared__ char dsm[];
    uint32_t sb0 = smem_u32(dsm);
    uint32_t sb = (sb0 + 127) & ~127u;
    char* base = dsm + (sb - sb0);
    float* rv = (float*)(base + 49152);

    const int tid = threadIdx.x, lane = tid & 31, wid = tid >> 5;
    const int wm = (wid & 1) << 6, wnc = (wid >> 1) << 4;
    const int bh = blockIdx.z, bz = bh >> 4, h = bh & 15;
    const int m0 = blockIdx.y << 7;
    const int gid = lane >> 2, tig = lane & 3;

    if (tid < 128) rv[tid] = g_rsum[(size_t)bh * SQ + m0 + tid];

    const __half* eb = g_e + (size_t)bh * ABH + (size_t)m0 * SQ;
    float* eo = EO + (size_t)bh * ABH;
    const bf16* vh = g_vh + (size_t)bz * SQ * DM + h * DK;   // fp16 payload

    float c2[4][2][4];
#pragma unroll
    for (int i = 0; i < 4; i++)
#pragma unroll
        for (int j = 0; j < 2; j++)
#pragma unroll
            for (int k = 0; k < 4; k++) c2[i][j][k] = 0.f;

    // prefetch chunk 0: P (128 rows x 64 halfs, row stride SQ) + V (64x64)
#pragma unroll
    for (int i = tid; i < 1024; i += 256) {
        int r = i >> 3, cc = i & 7;
        cp16(sb + swz(r, cc), eb + (size_t)r * SQ + cc * 8);
    }
    cp_tile<64>(sb + 32768, vh, tid);
    cp_commit();

    for (int kt = 0; kt < 32; kt++) {
        const int s = kt & 1;
        const uint32_t pS = sb + s * 16384;
        const uint32_t vS = sb + 32768 + s * 8192;
        if (kt < 31) {
            const int s1 = s ^ 1;
            const int ko = (kt + 1) * 64;
#pragma unroll
            for (int i = tid; i < 1024; i += 256) {
                int r = i >> 3, cc = i & 7;
                cp16(sb + s1 * 16384 + swz(r, cc), eb + (size_t)r * SQ + ko + cc * 8);
            }
            cp_tile<64>(sb + 32768 + s1 * 8192, vh + (size_t)ko * DM, tid);
            cp_commit();
            cp_wait<1>();
        } else {
            cp_wait<0>();
        }
        __syncthreads();   // stage s visible; rv visible (iter 0)

        // normalized attn write: P(s) smem (fp16) * rinv -> fp32 gmem
        const char* pB = base + (pS - sb);
#pragma unroll
        for (int idx = tid; idx < 2048; idx += 256) {
            int r = idx >> 4, cq = idx & 15;
            uint2 pv = *(const uint2*)(pB + swz(r, cq >> 1) + (cq & 1) * 8);
            __half2 p01 = *(__half2*)&pv.x;
            __half2 p23 = *(__half2*)&pv.y;
            float ri = rv[r];
            float4 o4 = make_float4(__half2float(p01.x) * ri,
                                    __half2float(p01.y) * ri,
                                    __half2float(p23.x) * ri,
                                    __half2float(p23.y) * ri);
            *(float4*)(eo + (size_t)(m0 + r) * SQ + kt * 64 + cq * 4) = o4;
        }

        // ctx accumulate: P(128x64 fp16) @ V(64x64 fp16)
#pragma unroll
        for (int kkc = 0; kkc < 4; kkc++) {
            uint32_t ap[4][4], b2[2][2];
#pragma unroll
            for (int f = 0; f < 4; f++)
                ldmA(ap[f], addrA(pS, wm + f * 16, kkc, lane));
#pragma unroll
            for (int f = 0; f < 2; f++)
                ldmBT(b2[f], addrBT(vS, kkc * 16, (wnc >> 3) + f, lane));
#pragma unroll
            for (int i = 0; i < 4; i++)
#pragma unroll
                for (int j = 0; j < 2; j++)
                    mma16816h(c2[i][j], ap[i], b2[j]);
        }
        __syncthreads();   // stage s free for next prefetch
    }

    // Epilogue: single rinv scale, ctx -> fp16 hi/lo into g_ch/g_cl
#pragma unroll
    for (int i = 0; i < 4; i++) {
        int lr0 = wm + i * 16 + gid;
        float ri0 = rv[lr0], ri1 = rv[lr0 + 8];
        int r0 = bz * SQ + m0 + lr0, r1 = r0 + 8;
#pragma unroll
        for (int j = 0; j < 2; j++) {
            int col = h * DK + wnc + j * 8 + tig * 2;
            uint32_t hh, ll;
            split2h(c2[i][j][0] * ri0, c2[i][j][1] * ri0, hh, ll);
            *(uint32_t*)(g_ch + (size_t)r0 * DM + col) = hh;
            *(uint32_t*)(g_cl + (size_t)r0 * DM + col) = ll;
            split2h(c2[i][j][2] * ri1, c2[i][j][3] * ri1, hh, ll);
            *(uint32_t*)(g_ch + (size_t)r1 * DM + col) = hh;
            *(uint32_t*)(g_cl + (size_t)r1 * DM + col) = ll;
        }
    }
}

// ---------------------------------------------------------------------------
__global__ void zero_rsum_kernel()
{
    g_rsum[blockIdx.x * 256 + threadIdx.x] = 0.f;
}

__global__ void inv_rsum_kernel()
{
    int i = blockIdx.x * 256 + threadIdx.x;
    g_rsum[i] = 1.0f / g_rsum[i];
}

// ---------------------------------------------------------------------------
// Residual + LayerNorm: y = LN(g_o + Q) * gamma + beta
// ---------------------------------------------------------------------------
__global__ void __launch_bounds__(256) ln_kernel(
    const float* __restrict__ Qin, const float* __restrict__ gam,
    const float* __restrict__ bet, float* __restrict__ Y)
{
    __shared__ float red[16];
    const int row = blockIdx.x;
    const int tid = threadIdx.x;
    const float* op = g_o + (size_t)row * DM;
    const float* qp = Qin + (size_t)row * DM;

    float4 o4 = *(const float4*)(op + tid * 4);
    float4 q4 = *(const float4*)(qp + tid * 4);
    float x0 = o4.x + q4.x;
    float x1 = o4.y + q4.y;
    float x2 = o4.z + q4.z;
    float x3 = o4.w + q4.w;
    float s  = x0 + x1 + x2 + x3;
    float s2 = x0 * x0 + x1 * x1 + x2 * x2 + x3 * x3;

#pragma unroll
    for (int off = 16; off > 0; off >>= 1) {
        s  += __shfl_xor_sync(0xffffffffu, s,  off);
        s2 += __shfl_xor_sync(0xffffffffu, s2, off);
    }
    int warp = tid >> 5, lane = tid & 31;
    if (lane == 0) { red[warp] = s; red[8 + warp] = s2; }
    __syncthreads();
    if (tid == 0) {
        float ts = 0.f, ts2 = 0.f;
#pragma unroll
        for (int w = 0; w < 8; w++) { ts += red[w]; ts2 += red[8 + w]; }
        red[0] = ts; red[8] = ts2;
    }
    __syncthreads();
    float mu  = red[0] * (1.0f / DM);
    float var = red[8] * (1.0f / DM) - mu * mu;
    float rstd = rsqrtf(var + 1e-5f);

    float4 g4 = *(const float4*)(gam + tid * 4);
    float4 b4 = *(const float4*)(bet + tid * 4);
    float4 y4;
    y4.x = (x0 - mu) * rstd * g4.x + b4.x;
    y4.y = (x1 - mu) * rstd * g4.y + b4.y;
    y4.z = (x2 - mu) * rstd * g4.z + b4.z;
    y4.w = (x3 - mu) * rstd * g4.w + b4.w;
    *(float4*)(Y + (size_t)row * DM + tid * 4) = y4;
}

// ---------------------------------------------------------------------------
extern "C" void kernel_launch(void* const* d_in, const int* in_sizes, int n_in,
                              void* d_out, int out_size)
{
    (void)in_sizes; (void)n_in; (void)out_size;
    const float* Q    = (const float*)d_in[0];
    const float* K    = (const float*)d_in[1];
    const float* V    = (const float*)d_in[2];
    const int*   mask = (const int*)  d_in[3];
    const float* Wq   = (const float*)d_in[4];
    const float* bq   = (const float*)d_in[5];
    const float* Wk   = (const float*)d_in[6];
    const float* bk   = (const float*)d_in[7];
    const float* Wv   = (const float*)d_in[8];
    const float* bv   = (const float*)d_in[9];
    const float* Wo   = (const float*)d_in[10];
    const float* bo   = (const float*)d_in[11];
    const float* lg   = (const float*)d_in[12];
    const float* lb   = (const float*)d_in[13];

    float* y    = (float*)d_out;
    float* attn = y + YSZ;

    bf16 *xh, *xl, *x2h, *x2l, *x3h, *x3l;
    bf16 *wh, *wl, *w2h, *w2l, *w3h, *w3l, *woh;
    bf16 *qh, *ql, *kh, *kl, *vh;
    cudaGetSymbolAddress((void**)&xh,  g_xh);
    cudaGetSymbolAddress((void**)&xl,  g_xl);
    cudaGetSymbolAddress((void**)&x2h, g_x2h);
    cudaGetSymbolAddress((void**)&x2l, g_x2l);
    cudaGetSymbolAddress((void**)&x3h, g_x3h);
    cudaGetSymbolAddress((void**)&x3l, g_x3l);
    cudaGetSymbolAddress((void**)&wh,  g_wh);
    cudaGetSymbolAddress((void**)&wl,  g_wl);
    cudaGetSymbolAddress((void**)&w2h, g_w2h);
    cudaGetSymbolAddress((void**)&w2l, g_w2l);
    cudaGetSymbolAddress((void**)&w3h, g_w3h);
    cudaGetSymbolAddress((void**)&w3l, g_w3l);
    cudaGetSymbolAddress((void**)&woh, g_woh);
    cudaGetSymbolAddress((void**)&qh,  g_qh);
    cudaGetSymbolAddress((void**)&ql,  g_ql);
    cudaGetSymbolAddress((void**)&kh,  g_kh);
    cudaGetSymbolAddress((void**)&kl,  g_kl);
    cudaGetSymbolAddress((void**)&vh,  g_vh);

    const int SM_PROJ  = 131072 + 128;
    const int SM_PROJO = 98304 + 128;
    const int SM_SCORE = 65536 + 1024;
    const int SM_CTX   = 49152 + 1024;
    cudaFuncSetAttribute(proj_mma,  cudaFuncAttributeMaxDynamicSharedMemorySize, SM_PROJ);
    cudaFuncSetAttribute(projo_mma, cudaFuncAttributeMaxDynamicSharedMemorySize, SM_PROJO);
    cudaFuncSetAttribute(score_mma, cudaFuncAttributeMaxDynamicSharedMemorySize, SM_SCORE);
    cudaFuncSetAttribute(ctx_mma,   cudaFuncAttributeMaxDynamicSharedMemorySize, SM_CTX);

    const int gx = (MROWS * DM / 4) / 256;
    const int gw = (DM * DM / 4) / 256;
    dim3 gp(DM / 128, MROWS / 128);          // (8, 64)

    conv_split<<<gw, 256>>>(Wq, wh,  wl);
    conv_split<<<gx, 256>>>(Q,  xh,  xl);
    conv_split<<<gw, 256>>>(Wk, w2h, w2l);
    conv_split<<<gx, 256>>>(K,  x2h, x2l);
    conv_split<<<gw, 256>>>(Wv, w3h, w3l);
    proj_mma<<<gp, 256, SM_PROJ>>>(xh, xl, wh, wl, bq, qh, ql, 0);
    conv_split<<<gx, 256>>>(V,  x3h, x3l);
    conv_h<<<gw, 256>>>(Wo, (__half*)woh);
    zero_rsum_kernel<<<(NB * NH * SQ) / 256, 256>>>();
    proj_mma<<<gp, 256, SM_PROJ>>>(x2h, x2l, w2h, w2l, bk, kh, kl, 0);
    proj_mma<<<gp, 256, SM_PROJ>>>(x3h, x3l, w3h, w3l, bv, vh, nullptr, 1);

    dim3 gs(SQ / 128, SQ / 128, NB * NH);    // (16, 16, 64)
    score_mma<<<gs, 256, SM_SCORE>>>(mask);

    inv_rsum_kernel<<<(NB * NH * SQ) / 256, 256>>>();

    dim3 gc(1, SQ / 128, NB * NH);           // (1, 16, 64)
    ctx_mma<<<gc, 256, SM_CTX>>>(attn);

    projo_mma<<<gp, 256, SM_PROJO>>>(bo);

    ln_kernel<<<MROWS, 256>>>(Q, lg, lb, y);
}

// round 16
// speedup vs baseline: 1.6913x; 1.4259x over previous
#include <cuda_runtime.h>
#include <cuda_bf16.h>
#include <cuda_fp16.h>
#include <stdint.h>

#define DM 1024
#define NH 16
#define DK 64
#define NB 4
#define SQ 2048
#define MROWS (NB * SQ)                 // 8192
#define YSZ ((size_t)MROWS * DM)
#define ABH ((size_t)SQ * SQ)

typedef __nv_bfloat16 bf16;   // raw 16-bit storage; payload is fp16 everywhere

// ---------------------------------------------------------------------------
// Scratch (allocation-free rule: __device__ globals)
// ---------------------------------------------------------------------------
__device__ bf16 g_xh[MROWS * DM],  g_xl[MROWS * DM];    // Q input (fp16 hi/lo)
__device__ bf16 g_x2h[MROWS * DM], g_x2l[MROWS * DM];   // K input
__device__ bf16 g_x3h[MROWS * DM], g_x3l[MROWS * DM];   // V input
__device__ bf16 g_ch[MROWS * DM],  g_cl[MROWS * DM];    // ctx output (fp16 hi/lo)
__device__ bf16 g_wh[DM * DM];                          // Wq (fp16 hi)
__device__ bf16 g_w2h[DM * DM];                         // Wk
__device__ bf16 g_w3h[DM * DM];                         // Wv
__device__ bf16 g_woh[DM * DM];                         // Wo
__device__ bf16 g_qh[MROWS * DM], g_ql[MROWS * DM];     // q (fp16 hi/lo)
__device__ bf16 g_kh[MROWS * DM];                       // k (fp16 hi)
__device__ bf16 g_vh[MROWS * DM];                       // v (fp16 hi)
__device__ __half g_e[(size_t)NB * NH * SQ * SQ];       // raw e, fp16 (536MB)
__device__ float g_o[MROWS * DM];
__device__ float g_rsum[NB * NH * SQ];

// ---------------------------------------------------------------------------
// Baseline-PTX helpers (sm_80-era: legal on plain compute_103)
// ---------------------------------------------------------------------------
__device__ __forceinline__ uint32_t smem_u32(const void* p) {
    uint32_t a;
    asm("{ .reg .u64 t; cvta.to.shared.u64 t, %1; cvt.u32.u64 %0, t; }"
        : "=r"(a) : "l"(p));
    return a;
}

__device__ __forceinline__ void mma16816h(float* c, const uint32_t* a, const uint32_t* b) {
    asm volatile(
        "mma.sync.aligned.m16n8k16.row.col.f32.f16.f16.f32 "
        "{%0,%1,%2,%3}, {%4,%5,%6,%7}, {%8,%9}, {%0,%1,%2,%3};"
        : "+f"(c[0]), "+f"(c[1]), "+f"(c[2]), "+f"(c[3])
        : "r"(a[0]), "r"(a[1]), "r"(a[2]), "r"(a[3]), "r"(b[0]), "r"(b[1]));
}

__device__ __forceinline__ void ldmA(uint32_t* r, uint32_t addr) {
    asm volatile("ldmatrix.sync.aligned.m8n8.x4.shared.b16 {%0,%1,%2,%3}, [%4];"
        : "=r"(r[0]), "=r"(r[1]), "=r"(r[2]), "=r"(r[3]) : "r"(addr));
}
__device__ __forceinline__ void ldmB(uint32_t* r, uint32_t addr) {
    asm volatile("ldmatrix.sync.aligned.m8n8.x2.shared.b16 {%0,%1}, [%2];"
        : "=r"(r[0]), "=r"(r[1]) : "r"(addr));
}
__device__ __forceinline__ void ldmBT(uint32_t* r, uint32_t addr) {
    asm volatile("ldmatrix.sync.aligned.m8n8.x2.trans.shared.b16 {%0,%1}, [%2];"
        : "=r"(r[0]), "=r"(r[1]) : "r"(addr));
}

__device__ __forceinline__ void cp16(uint32_t dst, const void* src) {
    asm volatile("cp.async.cg.shared.global [%0], [%1], 16;" :: "r"(dst), "l"(src));
}
__device__ __forceinline__ void cp_commit() {
    asm volatile("cp.async.commit_group;" ::: "memory");
}
template <int N>
__device__ __forceinline__ void cp_wait() {
    asm volatile("cp.async.wait_group %0;" :: "n"(N) : "memory");
}

// Tile rows are 64 halfwords = 128B, XOR-swizzled in 16B granules.
__device__ __forceinline__ uint32_t swz(int row, int c16) {
    return (uint32_t)(row * 128 + ((c16 ^ (row & 7)) << 4));
}
__device__ __forceinline__ uint32_t addrA(uint32_t base, int m_base, int kk, int lane) {
    int mat = lane >> 3;
    int row = m_base + (lane & 7) + ((mat & 1) << 3);
    int c16 = 2 * kk + (mat >> 1);
    return base + swz(row, c16);
}
__device__ __forceinline__ uint32_t addrB(uint32_t base, int n_base, int kk, int lane) {
    int l = lane & 15;
    int row = n_base + (l & 7);
    int c16 = 2 * kk + (l >> 3);
    return base + swz(row, c16);
}
__device__ __forceinline__ uint32_t addrBT(uint32_t base, int k_base, int n16, int lane) {
    int l = lane & 15;
    int row = k_base + (l & 7) + ((l >> 3) << 3);
    return base + swz(row, n16);
}

template <int R>
__device__ __forceinline__ void cp_tile(uint32_t dst, const bf16* src, int tid) {
    const int total = R * 8;
#pragma unroll
    for (int i = tid; i < total; i += 256) {
        int r = i >> 3, c = i & 7;
        cp16(dst + swz(r, c), src + (size_t)r * DM + c * 8);
    }
}

template <int R>
__device__ __forceinline__ void load_tile(char* dst, const bf16* src, int tid) {
    const int total = R * 8;
#pragma unroll
    for (int i = tid; i < total; i += 256) {
        int r = i >> 3, c = i & 7;
        uint4 v = *(const uint4*)(src + (size_t)r * DM + c * 8);
        *(uint4*)(dst + swz(r, c)) = v;
    }
}

__device__ __forceinline__ void split2h(float x, float y, uint32_t& h, uint32_t& l) {
    __half2 hh = __floats2half2_rn(x, y);
    __half2 ll = __floats2half2_rn(x - __half2float(hh.x),
                                   y - __half2float(hh.y));
    h = *(uint32_t*)&hh;
    l = *(uint32_t*)&ll;
}

// ---------------------------------------------------------------------------
// fp32 -> fp16 hi/lo split conversion
// ---------------------------------------------------------------------------
__global__ void __launch_bounds__(256) conv_splith(
    const float* __restrict__ x, bf16* __restrict__ h, bf16* __restrict__ l)
{
    size_t i = (size_t)(blockIdx.x * 256 + threadIdx.x) * 4;
    float4 v = *(const float4*)(x + i);
    uint32_t h01, l01, h23, l23;
    split2h(v.x, v.y, h01, l01);
    split2h(v.z, v.w, h23, l23);
    *(uint2*)(h + i) = make_uint2(h01, h23);
    *(uint2*)(l + i) = make_uint2(l01, l23);
}

// fp32 -> fp16 (hi only)
__global__ void __launch_bounds__(256) conv_h(
    const float* __restrict__ x, bf16* __restrict__ h)
{
    size_t i = (size_t)(blockIdx.x * 256 + threadIdx.x) * 4;
    float4 v = *(const float4*)(x + i);
    __half2 a = __floats2half2_rn(v.x, v.y);
    __half2 b = __floats2half2_rn(v.z, v.w);
    *(uint2*)(h + i) = make_uint2(*(uint32_t*)&a, *(uint32_t*)&b);
}

// ---------------------------------------------------------------------------
// Unified projection GEMM (fp16 2-product): C = (Xh+Xl) @ Wh^T + bias.
// 2-stage cp.async pipeline, stage stride 48KB: Ah@0, Al@16K, Bh@32K.
// Output: Cf fp32, else (Ch,Cl) fp16 hi/lo, else Ch fp16 hi only.
// ---------------------------------------------------------------------------
__global__ void __launch_bounds__(256) proj16(
    const bf16* __restrict__ Xh, const bf16* __restrict__ Xl,
    const bf16* __restrict__ Wh, const float* __restrict__ bias,
    float* __restrict__ Cf, bf16* __restrict__ Ch, bf16* __restrict__ Cl)
{
    extern __shared__ char dsm[];
    uint32_t sb0 = smem_u32(dsm);
    uint32_t sb = (sb0 + 127) & ~127u;

    const int tid = threadIdx.x, lane = tid & 31, wid = tid >> 5;
    const int wm = (wid & 1) << 6, wn = (wid >> 1) << 5;
    const int m0 = blockIdx.y << 7, n0 = blockIdx.x << 7;
    const int gid = lane >> 2, tig = lane & 3;

    const bf16* pXh = Xh + (size_t)m0 * DM;
    const bf16* pXl = Xl + (size_t)m0 * DM;
    const bf16* pWh = Wh + (size_t)n0 * DM;

    float c[4][4][4];
#pragma unroll
    for (int i = 0; i < 4; i++)
#pragma unroll
        for (int j = 0; j < 4; j++)
#pragma unroll
            for (int k = 0; k < 4; k++) c[i][j][k] = 0.f;

    cp_tile<128>(sb,         pXh, tid);
    cp_tile<128>(sb + 16384, pXl, tid);
    cp_tile<128>(sb + 32768, pWh, tid);
    cp_commit();

    for (int kt = 0; kt < 16; kt++) {
        const uint32_t st = sb + (kt & 1) * 49152;
        if (kt < 15) {
            const uint32_t nx = sb + ((kt + 1) & 1) * 49152;
            const int ko = (kt + 1) * 64;
            cp_tile<128>(nx,         pXh + ko, tid);
            cp_tile<128>(nx + 16384, pXl + ko, tid);
            cp_tile<128>(nx + 32768, pWh + ko, tid);
            cp_commit();
            cp_wait<1>();
        } else {
            cp_wait<0>();
        }
        __syncthreads();
#pragma unroll
        for (int kk = 0; kk < 4; kk++) {
            uint32_t ah[4][4], al[4][4], bh[4][2];
#pragma unroll
            for (int f = 0; f < 4; f++) {
                ldmA(ah[f], addrA(st,         wm + f * 16, kk, lane));
                ldmA(al[f], addrA(st + 16384, wm + f * 16, kk, lane));
                ldmB(bh[f], addrB(st + 32768, wn + f * 8,  kk, lane));
            }
#pragma unroll
            for (int i = 0; i < 4; i++)
#pragma unroll
                for (int j = 0; j < 4; j++) {
                    mma16816h(c[i][j], ah[i], bh[j]);
                    mma16816h(c[i][j], al[i], bh[j]);
                }
        }
        __syncthreads();
    }

#pragma unroll
    for (int i = 0; i < 4; i++) {
        int r0 = m0 + wm + i * 16 + gid, r1 = r0 + 8;
#pragma unroll
        for (int j = 0; j < 4; j++) {
            int col = n0 + wn + j * 8 + tig * 2;
            float2 bz = *(const float2*)(bias + col);
            float v00 = c[i][j][0] + bz.x, v01 = c[i][j][1] + bz.y;
            float v10 = c[i][j][2] + bz.x, v11 = c[i][j][3] + bz.y;
            if (Cf) {
                *(float2*)(Cf + (size_t)r0 * DM + col) = make_float2(v00, v01);
                *(float2*)(Cf + (size_t)r1 * DM + col) = make_float2(v10, v11);
            } else if (Cl) {
                uint32_t h, l;
                split2h(v00, v01, h, l);
                *(uint32_t*)(Ch + (size_t)r0 * DM + col) = h;
                *(uint32_t*)(Cl + (size_t)r0 * DM + col) = l;
                split2h(v10, v11, h, l);
                *(uint32_t*)(Ch + (size_t)r1 * DM + col) = h;
                *(uint32_t*)(Cl + (size_t)r1 * DM + col) = l;
            } else {
                __half2 a = __floats2half2_rn(v00, v01);
                __half2 b = __floats2half2_rn(v10, v11);
                *(uint32_t*)(Ch + (size_t)r0 * DM + col) = *(uint32_t*)&a;
                *(uint32_t*)(Ch + (size_t)r1 * DM + col) = *(uint32_t*)&b;
            }
        }
    }
}

// ---------------------------------------------------------------------------
// Score GEMM (fp16 2-product) + mask/exp epilogue + row sums (K=64).
// S = (qh+ql) @ kh^T / 8; writes raw e fp16 to g_e, rowsums to g_rsum.
// SMEM: qh@0 ql@16K kh@32K srow@48K  (~49KB -> 4 CTAs/SM)
// ---------------------------------------------------------------------------
__global__ void __launch_bounds__(256) score16(const int* __restrict__ mask)
{
    extern __shared__ char dsm[];
    uint32_t sb0 = smem_u32(dsm);
    uint32_t sb = (sb0 + 127) & ~127u;
    char* base = dsm + (sb - sb0);
    float* srow = (float*)(base + 49152);

    const int tid = threadIdx.x, lane = tid & 31, wid = tid >> 5;
    const int wm = (wid & 1) << 6, wn = (wid >> 1) << 5;
    const int bh = blockIdx.z, bz = bh >> 4, h = bh & 15;
    const int m0 = blockIdx.y << 7, n0 = blockIdx.x << 7;
    const int gid = lane >> 2, tig = lane & 3;

    if (tid < 128) srow[tid] = 0.f;

    const size_t qrow = (size_t)(bz * SQ + m0) * DM + h * DK;
    const size_t krow = (size_t)(bz * SQ + n0) * DM + h * DK;
    load_tile<128>(base,         g_qh + qrow, tid);
    load_tile<128>(base + 16384, g_ql + qrow, tid);
    load_tile<128>(base + 32768, g_kh + krow, tid);
    __syncthreads();

    float c[4][4][4];
#pragma unroll
    for (int i = 0; i < 4; i++)
#pragma unroll
        for (int j = 0; j < 4; j++)
#pragma unroll
            for (int k = 0; k < 4; k++) c[i][j][k] = 0.f;

#pragma unroll
    for (int kk = 0; kk < 4; kk++) {
        uint32_t ah[4][4], al[4][4], b2[4][2];
#pragma unroll
        for (int f = 0; f < 4; f++) {
            ldmA(ah[f], addrA(sb,         wm + f * 16, kk, lane));
            ldmA(al[f], addrA(sb + 16384, wm + f * 16, kk, lane));
            ldmB(b2[f], addrB(sb + 32768, wn + f * 8, kk, lane));
        }
#pragma unroll
        for (int i = 0; i < 4; i++)
#pragma unroll
            for (int j = 0; j < 4; j++) {
                mma16816h(c[i][j], ah[i], b2[j]);
                mma16816h(c[i][j], al[i], b2[j]);
            }
    }

    const int* mbase = mask + (size_t)bz * SQ * SQ;
    __half* ge = g_e + (size_t)bh * ABH;
    const float scale = 0.125f;

#pragma unroll
    for (int i = 0; i < 4; i++) {
        int r0 = m0 + wm + i * 16 + gid, r1 = r0 + 8;
        float rs0 = 0.f, rs1 = 0.f;
#pragma unroll
        for (int j = 0; j < 4; j++) {
            int col = n0 + wn + j * 8 + tig * 2;
            int2 mv0 = *(const int2*)(mbase + (size_t)r0 * SQ + col);
            int2 mv1 = *(const int2*)(mbase + (size_t)r1 * SQ + col);
            float e00 = mv0.x ? __expf(c[i][j][0] * scale) : 0.f;
            float e01 = mv0.y ? __expf(c[i][j][1] * scale) : 0.f;
            float e10 = mv1.x ? __expf(c[i][j][2] * scale) : 0.f;
            float e11 = mv1.y ? __expf(c[i][j][3] * scale) : 0.f;
            __half2 p0 = __floats2half2_rn(e00, e01);
            __half2 p1 = __floats2half2_rn(e10, e11);
            *(__half2*)(ge + (size_t)r0 * SQ + col) = p0;
            *(__half2*)(ge + (size_t)r1 * SQ + col) = p1;
            rs0 += e00 + e01;
            rs1 += e10 + e11;
        }
        rs0 += __shfl_xor_sync(0xffffffffu, rs0, 1);
        rs0 += __shfl_xor_sync(0xffffffffu, rs0, 2);
        rs1 += __shfl_xor_sync(0xffffffffu, rs1, 1);
        rs1 += __shfl_xor_sync(0xffffffffu, rs1, 2);
        if (tig == 0) {
            atomicAdd(&srow[wm + i * 16 + gid],     rs0);
            atomicAdd(&srow[wm + i * 16 + gid + 8], rs1);
        }
    }
    __syncthreads();
    if (tid < 128)
        atomicAdd(&g_rsum[(size_t)bh * SQ + m0 + tid], srow[tid]);
}

// ---------------------------------------------------------------------------
// Context GEMM (fp16 1-product): ctx = rinv * (E16 @ V16).
// cp.async streams fp16 e directly into MMA-ready swizzled P tiles.
// Writes normalized fp32 attn from smem. SMEM ~50KB -> 4 CTAs/SM.
// Layout: P(s)@s*16K | V(s)@32K+8K*s | rv@48K
// ---------------------------------------------------------------------------
__global__ void __launch_bounds__(256) ctx_mma(float* __restrict__ EO)
{
    extern __shared__ char dsm[];
    uint32_t sb0 = smem_u32(dsm);
    uint32_t sb = (sb0 + 127) & ~127u;
    char* base = dsm + (sb - sb0);
    float* rv = (float*)(base + 49152);

    const int tid = threadIdx.x, lane = tid & 31, wid = tid >> 5;
    const int wm = (wid & 1) << 6, wnc = (wid >> 1) << 4;
    const int bh = blockIdx.z, bz = bh >> 4, h = bh & 15;
    const int m0 = blockIdx.y << 7;
    const int gid = lane >> 2, tig = lane & 3;

    if (tid < 128) rv[tid] = g_rsum[(size_t)bh * SQ + m0 + tid];

    const __half* eb = g_e + (size_t)bh * ABH + (size_t)m0 * SQ;
    float* eo = EO + (size_t)bh * ABH;
    const bf16* vh = g_vh + (size_t)bz * SQ * DM + h * DK;

    float c2[4][2][4];
#pragma unroll
    for (int i = 0; i < 4; i++)
#pragma unroll
        for (int j = 0; j < 2; j++)
#pragma unroll
            for (int k = 0; k < 4; k++) c2[i][j][k] = 0.f;

#pragma unroll
    for (int i = tid; i < 1024; i += 256) {
        int r = i >> 3, cc = i & 7;
        cp16(sb + swz(r, cc), eb + (size_t)r * SQ + cc * 8);
    }
    cp_tile<64>(sb + 32768, vh, tid);
    cp_commit();

    for (int kt = 0; kt < 32; kt++) {
        const int s = kt & 1;
        const uint32_t pS = sb + s * 16384;
        const uint32_t vS = sb + 32768 + s * 8192;
        if (kt < 31) {
            const int s1 = s ^ 1;
            const int ko = (kt + 1) * 64;
#pragma unroll
            for (int i = tid; i < 1024; i += 256) {
                int r = i >> 3, cc = i & 7;
                cp16(sb + s1 * 16384 + swz(r, cc), eb + (size_t)r * SQ + ko + cc * 8);
            }
            cp_tile<64>(sb + 32768 + s1 * 8192, vh + (size_t)ko * DM, tid);
            cp_commit();
            cp_wait<1>();
        } else {
            cp_wait<0>();
        }
        __syncthreads();

        const char* pB = base + (pS - sb);
#pragma unroll
        for (int idx = tid; idx < 2048; idx += 256) {
            int r = idx >> 4, cq = idx & 15;
            uint2 pv = *(const uint2*)(pB + swz(r, cq >> 1) + (cq & 1) * 8);
            __half2 p01 = *(__half2*)&pv.x;
            __half2 p23 = *(__half2*)&pv.y;
            float ri = rv[r];
            float4 o4 = make_float4(__half2float(p01.x) * ri,
                                    __half2float(p01.y) * ri,
                                    __half2float(p23.x) * ri,
                                    __half2float(p23.y) * ri);
            *(float4*)(eo + (size_t)(m0 + r) * SQ + kt * 64 + cq * 4) = o4;
        }

#pragma unroll
        for (int kkc = 0; kkc < 4; kkc++) {
            uint32_t ap[4][4], b2[2][2];
#pragma unroll
            for (int f = 0; f < 4; f++)
                ldmA(ap[f], addrA(pS, wm + f * 16, kkc, lane));
#pragma unroll
            for (int f = 0; f < 2; f++)
                ldmBT(b2[f], addrBT(vS, kkc * 16, (wnc >> 3) + f, lane));
#pragma unroll
            for (int i = 0; i < 4; i++)
#pragma unroll
                for (int j = 0; j < 2; j++)
                    mma16816h(c2[i][j], ap[i], b2[j]);
        }
        __syncthreads();
    }

    // Epilogue: single rinv scale, ctx -> fp16 hi/lo into g_ch/g_cl
#pragma unroll
    for (int i = 0; i < 4; i++) {
        int lr0 = wm + i * 16 + gid;
        float ri0 = rv[lr0], ri1 = rv[lr0 + 8];
        int r0 = bz * SQ + m0 + lr0, r1 = r0 + 8;
#pragma unroll
        for (int j = 0; j < 2; j++) {
            int col = h * DK + wnc + j * 8 + tig * 2;
            uint32_t hh, ll;
            split2h(c2[i][j][0] * ri0, c2[i][j][1] * ri0, hh, ll);
            *(uint32_t*)(g_ch + (size_t)r0 * DM + col) = hh;
            *(uint32_t*)(g_cl + (size_t)r0 * DM + col) = ll;
            split2h(c2[i][j][2] * ri1, c2[i][j][3] * ri1, hh, ll);
            *(uint32_t*)(g_ch + (size_t)r1 * DM + col) = hh;
            *(uint32_t*)(g_cl + (size_t)r1 * DM + col) = ll;
        }
    }
}

// ---------------------------------------------------------------------------
__global__ void zero_rsum_kernel()
{
    g_rsum[blockIdx.x * 256 + threadIdx.x] = 0.f;
}

__global__ void inv_rsum_kernel()
{
    int i = blockIdx.x * 256 + threadIdx.x;
    g_rsum[i] = 1.0f / g_rsum[i];
}

// ---------------------------------------------------------------------------
// Residual + LayerNorm: y = LN(g_o + Q) * gamma + beta
// ---------------------------------------------------------------------------
__global__ void __launch_bounds__(256) ln_kernel(
    const float* __restrict__ Qin, const float* __restrict__ gam,
    const float* __restrict__ bet, float* __restrict__ Y)
{
    __shared__ float red[16];
    const int row = blockIdx.x;
    const int tid = threadIdx.x;
    const float* op = g_o + (size_t)row * DM;
    const float* qp = Qin + (size_t)row * DM;

    float4 o4 = *(const float4*)(op + tid * 4);
    float4 q4 = *(const float4*)(qp + tid * 4);
    float x0 = o4.x + q4.x;
    float x1 = o4.y + q4.y;
    float x2 = o4.z + q4.z;
    float x3 = o4.w + q4.w;
    float s  = x0 + x1 + x2 + x3;
    float s2 = x0 * x0 + x1 * x1 + x2 * x2 + x3 * x3;

#pragma unroll
    for (int off = 16; off > 0; off >>= 1) {
        s  += __shfl_xor_sync(0xffffffffu, s,  off);
        s2 += __shfl_xor_sync(0xffffffffu, s2, off);
    }
    int warp = tid >> 5, lane = tid & 31;
    if (lane == 0) { red[warp] = s; red[8 + warp] = s2; }
    __syncthreads();
    if (tid == 0) {
        float ts = 0.f, ts2 = 0.f;
#pragma unroll
        for (int w = 0; w < 8; w++) { ts += red[w]; ts2 += red[8 + w]; }
        red[0] = ts; red[8] = ts2;
    }
    __syncthreads();
    float mu  = red[0] * (1.0f / DM);
    float var = red[8] * (1.0f / DM) - mu * mu;
    float rstd = rsqrtf(var + 1e-5f);

    float4 g4 = *(const float4*)(gam + tid * 4);
    float4 b4 = *(const float4*)(bet + tid * 4);
    float4 y4;
    y4.x = (x0 - mu) * rstd * g4.x + b4.x;
    y4.y = (x1 - mu) * rstd * g4.y + b4.y;
    y4.z = (x2 - mu) * rstd * g4.z + b4.z;
    y4.w = (x3 - mu) * rstd * g4.w + b4.w;
    *(float4*)(Y + (size_t)row * DM + tid * 4) = y4;
}

// ---------------------------------------------------------------------------
extern "C" void kernel_launch(void* const* d_in, const int* in_sizes, int n_in,
                              void* d_out, int out_size)
{
    (void)in_sizes; (void)n_in; (void)out_size;
    const float* Q    = (const float*)d_in[0];
    const float* K    = (const float*)d_in[1];
    const float* V    = (const float*)d_in[2];
    const int*   mask = (const int*)  d_in[3];
    const float* Wq   = (const float*)d_in[4];
    const float* bq   = (const float*)d_in[5];
    const float* Wk   = (const float*)d_in[6];
    const float* bk   = (const float*)d_in[7];
    const float* Wv   = (const float*)d_in[8];
    const float* bv   = (const float*)d_in[9];
    const float* Wo   = (const float*)d_in[10];
    const float* bo   = (const float*)d_in[11];
    const float* lg   = (const float*)d_in[12];
    const float* lb   = (const float*)d_in[13];

    float* y    = (float*)d_out;
    float* attn = y + YSZ;

    bf16 *xh, *xl, *x2h, *x2l, *x3h, *x3l;
    bf16 *wh, *w2h, *w3h, *woh, *ch, *cl;
    bf16 *qh, *ql, *kh, *vh;
    float *po;
    cudaGetSymbolAddress((void**)&xh,  g_xh);
    cudaGetSymbolAddress((void**)&xl,  g_xl);
    cudaGetSymbolAddress((void**)&x2h, g_x2h);
    cudaGetSymbolAddress((void**)&x2l, g_x2l);
    cudaGetSymbolAddress((void**)&x3h, g_x3h);
    cudaGetSymbolAddress((void**)&x3l, g_x3l);
    cudaGetSymbolAddress((void**)&wh,  g_wh);
    cudaGetSymbolAddress((void**)&w2h, g_w2h);
    cudaGetSymbolAddress((void**)&w3h, g_w3h);
    cudaGetSymbolAddress((void**)&woh, g_woh);
    cudaGetSymbolAddress((void**)&ch,  g_ch);
    cudaGetSymbolAddress((void**)&cl,  g_cl);
    cudaGetSymbolAddress((void**)&qh,  g_qh);
    cudaGetSymbolAddress((void**)&ql,  g_ql);
    cudaGetSymbolAddress((void**)&kh,  g_kh);
    cudaGetSymbolAddress((void**)&vh,  g_vh);
    cudaGetSymbolAddress((void**)&po,  g_o);

    const int SM_PROJ  = 98304 + 128;
    const int SM_SCORE = 49152 + 1024;
    const int SM_CTX   = 49152 + 1024;
    cudaFuncSetAttribute(proj16,  cudaFuncAttributeMaxDynamicSharedMemorySize, SM_PROJ);
    cudaFuncSetAttribute(score16, cudaFuncAttributeMaxDynamicSharedMemorySize, SM_SCORE);
    cudaFuncSetAttribute(ctx_mma, cudaFuncAttributeMaxDynamicSharedMemorySize, SM_CTX);

    const int gx = (MROWS * DM / 4) / 256;
    const int gw = (DM * DM / 4) / 256;
    dim3 gp(DM / 128, MROWS / 128);          // (8, 64)

    conv_h<<<gw, 256>>>(Wq, wh);
    conv_splith<<<gx, 256>>>(Q, xh, xl);
    conv_h<<<gw, 256>>>(Wk, w2h);
    conv_splith<<<gx, 256>>>(K, x2h, x2l);
    conv_h<<<gw, 256>>>(Wv, w3h);
    proj16<<<gp, 256, SM_PROJ>>>(xh, xl, wh, bq, nullptr, qh, ql);
    conv_splith<<<gx, 256>>>(V, x3h, x3l);
    conv_h<<<gw, 256>>>(Wo, woh);
    zero_rsum_kernel<<<(NB * NH * SQ) / 256, 256>>>();
    proj16<<<gp, 256, SM_PROJ>>>(x2h, x2l, w2h, bk, nullptr, kh, nullptr);
    proj16<<<gp, 256, SM_PROJ>>>(x3h, x3l, w3h, bv, nullptr, vh, nullptr);

    dim3 gs(SQ / 128, SQ / 128, NB * NH);    // (16, 16, 64)
    score16<<<gs, 256, SM_SCORE>>>(mask);

    inv_rsum_kernel<<<(NB * NH * SQ) / 256, 256>>>();

    dim3 gc(1, SQ / 128, NB * NH);           // (1, 16, 64)
    ctx_mma<<<gc, 256, SM_CTX>>>(attn);

    proj16<<<gp, 256, SM_PROJ>>>(ch, cl, woh, bo, po, nullptr, nullptr);

    ln_kernel<<<MROWS, 256>>>(Q, lg, lb, y);
}

// round 17
// speedup vs baseline: 1.9281x; 1.1400x over previous
#include <cuda_runtime.h>
#include <cuda_bf16.h>
#include <cuda_fp16.h>
#include <stdint.h>

#define DM 1024
#define NH 16
#define DK 64
#define NB 4
#define SQ 2048
#define MROWS (NB * SQ)                 // 8192
#define YSZ ((size_t)MROWS * DM)
#define ABH ((size_t)SQ * SQ)

typedef __nv_bfloat16 bf16;   // raw 16-bit storage; payload is fp16 everywhere

// ---------------------------------------------------------------------------
// Scratch (allocation-free rule: __device__ globals)
// ---------------------------------------------------------------------------
__device__ bf16 g_xh[MROWS * DM];                       // Q input (fp16 hi)
__device__ bf16 g_x2h[MROWS * DM];                      // K input
__device__ bf16 g_x3h[MROWS * DM];                      // V input
__device__ bf16 g_ch[MROWS * DM];                       // ctx output (fp16 hi)
__device__ bf16 g_wh[DM * DM];                          // Wq (fp16 hi)
__device__ bf16 g_w2h[DM * DM];                         // Wk
__device__ bf16 g_w3h[DM * DM];                         // Wv
__device__ bf16 g_woh[DM * DM];                         // Wo
__device__ bf16 g_qh[MROWS * DM], g_ql[MROWS * DM];     // q (fp16 hi/lo)
__device__ bf16 g_kh[MROWS * DM];                       // k (fp16 hi)
__device__ bf16 g_vh[MROWS * DM];                       // v (fp16 hi)
__device__ __half g_e[(size_t)NB * NH * SQ * SQ];       // raw e, fp16 (536MB)
__device__ float g_o[MROWS * DM];
__device__ float g_rsum[NB * NH * SQ];

// ---------------------------------------------------------------------------
// Baseline-PTX helpers (sm_80-era: legal on plain compute_103)
// ---------------------------------------------------------------------------
__device__ __forceinline__ uint32_t smem_u32(const void* p) {
    uint32_t a;
    asm("{ .reg .u64 t; cvta.to.shared.u64 t, %1; cvt.u32.u64 %0, t; }"
        : "=r"(a) : "l"(p));
    return a;
}

__device__ __forceinline__ void mma16816h(float* c, const uint32_t* a, const uint32_t* b) {
    asm volatile(
        "mma.sync.aligned.m16n8k16.row.col.f32.f16.f16.f32 "
        "{%0,%1,%2,%3}, {%4,%5,%6,%7}, {%8,%9}, {%0,%1,%2,%3};"
        : "+f"(c[0]), "+f"(c[1]), "+f"(c[2]), "+f"(c[3])
        : "r"(a[0]), "r"(a[1]), "r"(a[2]), "r"(a[3]), "r"(b[0]), "r"(b[1]));
}

__device__ __forceinline__ void ldmA(uint32_t* r, uint32_t addr) {
    asm volatile("ldmatrix.sync.aligned.m8n8.x4.shared.b16 {%0,%1,%2,%3}, [%4];"
        : "=r"(r[0]), "=r"(r[1]), "=r"(r[2]), "=r"(r[3]) : "r"(addr));
}
__device__ __forceinline__ void ldmB(uint32_t* r, uint32_t addr) {
    asm volatile("ldmatrix.sync.aligned.m8n8.x2.shared.b16 {%0,%1}, [%2];"
        : "=r"(r[0]), "=r"(r[1]) : "r"(addr));
}
__device__ __forceinline__ void ldmBT(uint32_t* r, uint32_t addr) {
    asm volatile("ldmatrix.sync.aligned.m8n8.x2.trans.shared.b16 {%0,%1}, [%2];"
        : "=r"(r[0]), "=r"(r[1]) : "r"(addr));
}

__device__ __forceinline__ void cp16(uint32_t dst, const void* src) {
    asm volatile("cp.async.cg.shared.global [%0], [%1], 16;" :: "r"(dst), "l"(src));
}
__device__ __forceinline__ void cp_commit() {
    asm volatile("cp.async.commit_group;" ::: "memory");
}
template <int N>
__device__ __forceinline__ void cp_wait() {
    asm volatile("cp.async.wait_group %0;" :: "n"(N) : "memory");
}

// Tile rows are 64 halfwords = 128B, XOR-swizzled in 16B granules.
__device__ __forceinline__ uint32_t swz(int row, int c16) {
    return (uint32_t)(row * 128 + ((c16 ^ (row & 7)) << 4));
}
__device__ __forceinline__ uint32_t addrA(uint32_t base, int m_base, int kk, int lane) {
    int mat = lane >> 3;
    int row = m_base + (lane & 7) + ((mat & 1) << 3);
    int c16 = 2 * kk + (mat >> 1);
    return base + swz(row, c16);
}
__device__ __forceinline__ uint32_t addrB(uint32_t base, int n_base, int kk, int lane) {
    int l = lane & 15;
    int row = n_base + (l & 7);
    int c16 = 2 * kk + (l >> 3);
    return base + swz(row, c16);
}
__device__ __forceinline__ uint32_t addrBT(uint32_t base, int k_base, int n16, int lane) {
    int l = lane & 15;
    int row = k_base + (l & 7) + ((l >> 3) << 3);
    return base + swz(row, n16);
}

template <int R>
__device__ __forceinline__ void cp_tile(uint32_t dst, const bf16* src, int tid) {
    const int total = R * 8;
#pragma unroll
    for (int i = tid; i < total; i += 256) {
        int r = i >> 3, c = i & 7;
        cp16(dst + swz(r, c), src + (size_t)r * DM + c * 8);
    }
}

template <int R>
__device__ __forceinline__ void load_tile(char* dst, const bf16* src, int tid) {
    const int total = R * 8;
#pragma unroll
    for (int i = tid; i < total; i += 256) {
        int r = i >> 3, c = i & 7;
        uint4 v = *(const uint4*)(src + (size_t)r * DM + c * 8);
        *(uint4*)(dst + swz(r, c)) = v;
    }
}

__device__ __forceinline__ void split2h(float x, float y, uint32_t& h, uint32_t& l) {
    __half2 hh = __floats2half2_rn(x, y);
    __half2 ll = __floats2half2_rn(x - __half2float(hh.x),
                                   y - __half2float(hh.y));
    h = *(uint32_t*)&hh;
    l = *(uint32_t*)&ll;
}

// ---------------------------------------------------------------------------
// fp32 -> fp16 (hi only)
// ---------------------------------------------------------------------------
__global__ void __launch_bounds__(256) conv_h(
    const float* __restrict__ x, bf16* __restrict__ h)
{
    size_t i = (size_t)(blockIdx.x * 256 + threadIdx.x) * 4;
    float4 v = *(const float4*)(x + i);
    __half2 a = __floats2half2_rn(v.x, v.y);
    __half2 b = __floats2half2_rn(v.z, v.w);
    *(uint2*)(h + i) = make_uint2(*(uint32_t*)&a, *(uint32_t*)&b);
}

// ---------------------------------------------------------------------------
// Unified projection GEMM (fp16 1-product): C = Xh @ Wh^T + bias.
// 2-stage cp.async pipeline, stage stride 32KB: A@0, B@16K.
// Output: Cf fp32, else (Ch,Cl) fp16 hi/lo, else Ch fp16 hi only.
// ---------------------------------------------------------------------------
__global__ void __launch_bounds__(256) proj16(
    const bf16* __restrict__ Xh, const bf16* __restrict__ Wh,
    const float* __restrict__ bias,
    float* __restrict__ Cf, bf16* __restrict__ Ch, bf16* __restrict__ Cl)
{
    extern __shared__ char dsm[];
    uint32_t sb0 = smem_u32(dsm);
    uint32_t sb = (sb0 + 127) & ~127u;

    const int tid = threadIdx.x, lane = tid & 31, wid = tid >> 5;
    const int wm = (wid & 1) << 6, wn = (wid >> 1) << 5;
    const int m0 = blockIdx.y << 7, n0 = blockIdx.x << 7;
    const int gid = lane >> 2, tig = lane & 3;

    const bf16* pXh = Xh + (size_t)m0 * DM;
    const bf16* pWh = Wh + (size_t)n0 * DM;

    float c[4][4][4];
#pragma unroll
    for (int i = 0; i < 4; i++)
#pragma unroll
        for (int j = 0; j < 4; j++)
#pragma unroll
            for (int k = 0; k < 4; k++) c[i][j][k] = 0.f;

    cp_tile<128>(sb,         pXh, tid);
    cp_tile<128>(sb + 16384, pWh, tid);
    cp_commit();

    for (int kt = 0; kt < 16; kt++) {
        const uint32_t st = sb + (kt & 1) * 32768;
        if (kt < 15) {
            const uint32_t nx = sb + ((kt + 1) & 1) * 32768;
            const int ko = (kt + 1) * 64;
            cp_tile<128>(nx,         pXh + ko, tid);
            cp_tile<128>(nx + 16384, pWh + ko, tid);
            cp_commit();
            cp_wait<1>();
        } else {
            cp_wait<0>();
        }
        __syncthreads();
#pragma unroll
        for (int kk = 0; kk < 4; kk++) {
            uint32_t ah[4][4], bh[4][2];
#pragma unroll
            for (int f = 0; f < 4; f++) {
                ldmA(ah[f], addrA(st,         wm + f * 16, kk, lane));
                ldmB(bh[f], addrB(st + 16384, wn + f * 8,  kk, lane));
            }
#pragma unroll
            for (int i = 0; i < 4; i++)
#pragma unroll
                for (int j = 0; j < 4; j++)
                    mma16816h(c[i][j], ah[i], bh[j]);
        }
        __syncthreads();
    }

#pragma unroll
    for (int i = 0; i < 4; i++) {
        int r0 = m0 + wm + i * 16 + gid, r1 = r0 + 8;
#pragma unroll
        for (int j = 0; j < 4; j++) {
            int col = n0 + wn + j * 8 + tig * 2;
            float2 bz = *(const float2*)(bias + col);
            float v00 = c[i][j][0] + bz.x, v01 = c[i][j][1] + bz.y;
            float v10 = c[i][j][2] + bz.x, v11 = c[i][j][3] + bz.y;
            if (Cf) {
                *(float2*)(Cf + (size_t)r0 * DM + col) = make_float2(v00, v01);
                *(float2*)(Cf + (size_t)r1 * DM + col) = make_float2(v10, v11);
            } else if (Cl) {
                uint32_t h, l;
                split2h(v00, v01, h, l);
                *(uint32_t*)(Ch + (size_t)r0 * DM + col) = h;
                *(uint32_t*)(Cl + (size_t)r0 * DM + col) = l;
                split2h(v10, v11, h, l);
                *(uint32_t*)(Ch + (size_t)r1 * DM + col) = h;
                *(uint32_t*)(Cl + (size_t)r1 * DM + col) = l;
            } else {
                __half2 a = __floats2half2_rn(v00, v01);
                __half2 b = __floats2half2_rn(v10, v11);
                *(uint32_t*)(Ch + (size_t)r0 * DM + col) = *(uint32_t*)&a;
                *(uint32_t*)(Ch + (size_t)r1 * DM + col) = *(uint32_t*)&b;
            }
        }
    }
}

// ---------------------------------------------------------------------------
// Score GEMM (fp16 2-product) + mask/exp epilogue + row sums (K=64).
// S = (qh+ql) @ kh^T / 8; writes raw e fp16 to g_e, rowsums to g_rsum.
// SMEM: qh@0 ql@16K kh@32K srow@48K  (~49KB -> 4 CTAs/SM)
// ---------------------------------------------------------------------------
__global__ void __launch_bounds__(256) score16(const int* __restrict__ mask)
{
    extern __shared__ char dsm[];
    uint32_t sb0 = smem_u32(dsm);
    uint32_t sb = (sb0 + 127) & ~127u;
    char* base = dsm + (sb - sb0);
    float* srow = (float*)(base + 49152);

    const int tid = threadIdx.x, lane = tid & 31, wid = tid >> 5;
    const int wm = (wid & 1) << 6, wn = (wid >> 1) << 5;
    const int bh = blockIdx.z, bz = bh >> 4, h = bh & 15;
    const int m0 = blockIdx.y << 7, n0 = blockIdx.x << 7;
    const int gid = lane >> 2, tig = lane & 3;

    if (tid < 128) srow[tid] = 0.f;

    const size_t qrow = (size_t)(bz * SQ + m0) * DM + h * DK;
    const size_t krow = (size_t)(bz * SQ + n0) * DM + h * DK;
    load_tile<128>(base,         g_qh + qrow, tid);
    load_tile<128>(base + 16384, g_ql + qrow, tid);
    load_tile<128>(base + 32768, g_kh + krow, tid);
    __syncthreads();

    float c[4][4][4];
#pragma unroll
    for (int i = 0; i < 4; i++)
#pragma unroll
        for (int j = 0; j < 4; j++)
#pragma unroll
            for (int k = 0; k < 4; k++) c[i][j][k] = 0.f;

#pragma unroll
    for (int kk = 0; kk < 4; kk++) {
        uint32_t ah[4][4], al[4][4], b2[4][2];
#pragma unroll
        for (int f = 0; f < 4; f++) {
            ldmA(ah[f], addrA(sb,         wm + f * 16, kk, lane));
            ldmA(al[f], addrA(sb + 16384, wm + f * 16, kk, lane));
            ldmB(b2[f], addrB(sb + 32768, wn + f * 8, kk, lane));
        }
#pragma unroll
        for (int i = 0; i < 4; i++)
#pragma unroll
            for (int j = 0; j < 4; j++) {
                mma16816h(c[i][j], ah[i], b2[j]);
                mma16816h(c[i][j], al[i], b2[j]);
            }
    }

    const int* mbase = mask + (size_t)bz * SQ * SQ;
    __half* ge = g_e + (size_t)bh * ABH;
    const float scale = 0.125f;

#pragma unroll
    for (int i = 0; i < 4; i++) {
        int r0 = m0 + wm + i * 16 + gid, r1 = r0 + 8;
        float rs0 = 0.f, rs1 = 0.f;
#pragma unroll
        for (int j = 0; j < 4; j++) {
            int col = n0 + wn + j * 8 + tig * 2;
            int2 mv0 = *(const int2*)(mbase + (size_t)r0 * SQ + col);
            int2 mv1 = *(const int2*)(mbase + (size_t)r1 * SQ + col);
            float e00 = mv0.x ? __expf(c[i][j][0] * scale) : 0.f;
            float e01 = mv0.y ? __expf(c[i][j][1] * scale) : 0.f;
            float e10 = mv1.x ? __expf(c[i][j][2] * scale) : 0.f;
            float e11 = mv1.y ? __expf(c[i][j][3] * scale) : 0.f;
            __half2 p0 = __floats2half2_rn(e00, e01);
            __half2 p1 = __floats2half2_rn(e10, e11);
            *(__half2*)(ge + (size_t)r0 * SQ + col) = p0;
            *(__half2*)(ge + (size_t)r1 * SQ + col) = p1;
            rs0 += e00 + e01;
            rs1 += e10 + e11;
        }
        rs0 += __shfl_xor_sync(0xffffffffu, rs0, 1);
        rs0 += __shfl_xor_sync(0xffffffffu, rs0, 2);
        rs1 += __shfl_xor_sync(0xffffffffu, rs1, 1);
        rs1 += __shfl_xor_sync(0xffffffffu, rs1, 2);
        if (tig == 0) {
            atomicAdd(&srow[wm + i * 16 + gid],     rs0);
            atomicAdd(&srow[wm + i * 16 + gid + 8], rs1);
        }
    }
    __syncthreads();
    if (tid < 128)
        atomicAdd(&g_rsum[(size_t)bh * SQ + m0 + tid], srow[tid]);
}

// ---------------------------------------------------------------------------
// Context GEMM (fp16 1-product): ctx = rinv * (E16 @ V16).
// cp.async streams fp16 e directly into MMA-ready swizzled P tiles.
// Reciprocal of rowsum computed here (inv_rsum folded in).
// Writes normalized fp32 attn from smem; ctx -> fp16 hi only (g_ch).
// SMEM ~50KB -> 4 CTAs/SM. Layout: P(s)@s*16K | V(s)@32K+8K*s | rv@48K
// ---------------------------------------------------------------------------
__global__ void __launch_bounds__(256) ctx_mma(float* __restrict__ EO)
{
    extern __shared__ char dsm[];
    uint32_t sb0 = smem_u32(dsm);
    uint32_t sb = (sb0 + 127) & ~127u;
    char* base = dsm + (sb - sb0);
    float* rv = (float*)(base + 49152);

    const int tid = threadIdx.x, lane = tid & 31, wid = tid >> 5;
    const int wm = (wid & 1) << 6, wnc = (wid >> 1) << 4;
    const int bh = blockIdx.z, bz = bh >> 4, h = bh & 15;
    const int m0 = blockIdx.y << 7;
    const int gid = lane >> 2, tig = lane & 3;

    if (tid < 128) rv[tid] = 1.0f / g_rsum[(size_t)bh * SQ + m0 + tid];

    const __half* eb = g_e + (size_t)bh * ABH + (size_t)m0 * SQ;
    float* eo = EO + (size_t)bh * ABH;
    const bf16* vh = g_vh + (size_t)bz * SQ * DM + h * DK;

    float c2[4][2][4];
#pragma unroll
    for (int i = 0; i < 4; i++)
#pragma unroll
        for (int j = 0; j < 2; j++)
#pragma unroll
            for (int k = 0; k < 4; k++) c2[i][j][k] = 0.f;

#pragma unroll
    for (int i = tid; i < 1024; i += 256) {
        int r = i >> 3, cc = i & 7;
        cp16(sb + swz(r, cc), eb + (size_t)r * SQ + cc * 8);
    }
    cp_tile<64>(sb + 32768, vh, tid);
    cp_commit();

    for (int kt = 0; kt < 32; kt++) {
        const int s = kt & 1;
        const uint32_t pS = sb + s * 16384;
        const uint32_t vS = sb + 32768 + s * 8192;
        if (kt < 31) {
            const int s1 = s ^ 1;
            const int ko = (kt + 1) * 64;
#pragma unroll
            for (int i = tid; i < 1024; i += 256) {
                int r = i >> 3, cc = i & 7;
                cp16(sb + s1 * 16384 + swz(r, cc), eb + (size_t)r * SQ + ko + cc * 8);
            }
            cp_tile<64>(sb + 32768 + s1 * 8192, vh + (size_t)ko * DM, tid);
            cp_commit();
            cp_wait<1>();
        } else {
            cp_wait<0>();
        }
        __syncthreads();

        const char* pB = base + (pS - sb);
#pragma unroll
        for (int idx = tid; idx < 2048; idx += 256) {
            int r = idx >> 4, cq = idx & 15;
            uint2 pv = *(const uint2*)(pB + swz(r, cq >> 1) + (cq & 1) * 8);
            __half2 p01 = *(__half2*)&pv.x;
            __half2 p23 = *(__half2*)&pv.y;
            float ri = rv[r];
            float4 o4 = make_float4(__half2float(p01.x) * ri,
                                    __half2float(p01.y) * ri,
                                    __half2float(p23.x) * ri,
                                    __half2float(p23.y) * ri);
            *(float4*)(eo + (size_t)(m0 + r) * SQ + kt * 64 + cq * 4) = o4;
        }

#pragma unroll
        for (int kkc = 0; kkc < 4; kkc++) {
            uint32_t ap[4][4], b2[2][2];
#pragma unroll
            for (int f = 0; f < 4; f++)
                ldmA(ap[f], addrA(pS, wm + f * 16, kkc, lane));
#pragma unroll
            for (int f = 0; f < 2; f++)
                ldmBT(b2[f], addrBT(vS, kkc * 16, (wnc >> 3) + f, lane));
#pragma unroll
            for (int i = 0; i < 4; i++)
#pragma unroll
                for (int j = 0; j < 2; j++)
                    mma16816h(c2[i][j], ap[i], b2[j]);
        }
        __syncthreads();
    }

    // Epilogue: single rinv scale, ctx -> fp16 hi into g_ch
#pragma unroll
    for (int i = 0; i < 4; i++) {
        int lr0 = wm + i * 16 + gid;
        float ri0 = rv[lr0], ri1 = rv[lr0 + 8];
        int r0 = bz * SQ + m0 + lr0, r1 = r0 + 8;
#pragma unroll
        for (int j = 0; j < 2; j++) {
            int col = h * DK + wnc + j * 8 + tig * 2;
            __half2 a = __floats2half2_rn(c2[i][j][0] * ri0, c2[i][j][1] * ri0);
            __half2 b = __floats2half2_rn(c2[i][j][2] * ri1, c2[i][j][3] * ri1);
            *(uint32_t*)(g_ch + (size_t)r0 * DM + col) = *(uint32_t*)&a;
            *(uint32_t*)(g_ch + (size_t)r1 * DM + col) = *(uint32_t*)&b;
        }
    }
}

// ---------------------------------------------------------------------------
__global__ void zero_rsum_kernel()
{
    g_rsum[blockIdx.x * 256 + threadIdx.x] = 0.f;
}

// ---------------------------------------------------------------------------
// Residual + LayerNorm: y = LN(g_o + Q) * gamma + beta
// ---------------------------------------------------------------------------
__global__ void __launch_bounds__(256) ln_kernel(
    const float* __restrict__ Qin, const float* __restrict__ gam,
    const float* __restrict__ bet, float* __restrict__ Y)
{
    __shared__ float red[16];
    const int row = blockIdx.x;
    const int tid = threadIdx.x;
    const float* op = g_o + (size_t)row * DM;
    const float* qp = Qin + (size_t)row * DM;

    float4 o4 = *(const float4*)(op + tid * 4);
    float4 q4 = *(const float4*)(qp + tid * 4);
    float x0 = o4.x + q4.x;
    float x1 = o4.y + q4.y;
    float x2 = o4.z + q4.z;
    float x3 = o4.w + q4.w;
    float s  = x0 + x1 + x2 + x3;
    float s2 = x0 * x0 + x1 * x1 + x2 * x2 + x3 * x3;

#pragma unroll
    for (int off = 16; off > 0; off >>= 1) {
        s  += __shfl_xor_sync(0xffffffffu, s,  off);
        s2 += __shfl_xor_sync(0xffffffffu, s2, off);
    }
    int warp = tid >> 5, lane = tid & 31;
    if (lane == 0) { red[warp] = s; red[8 + warp] = s2; }
    __syncthreads();
    if (tid == 0) {
        float ts = 0.f, ts2 = 0.f;
#pragma unroll
        for (int w = 0; w < 8; w++) { ts += red[w]; ts2 += red[8 + w]; }
        red[0] = ts; red[8] = ts2;
    }
    __syncthreads();
    float mu  = red[0] * (1.0f / DM);
    float var = red[8] * (1.0f / DM) - mu * mu;
    float rstd = rsqrtf(var + 1e-5f);

    float4 g4 = *(const float4*)(gam + tid * 4);
    float4 b4 = *(const float4*)(bet + tid * 4);
    float4 y4;
    y4.x = (x0 - mu) * rstd * g4.x + b4.x;
    y4.y = (x1 - mu) * rstd * g4.y + b4.y;
    y4.z = (x2 - mu) * rstd * g4.z + b4.z;
    y4.w = (x3 - mu) * rstd * g4.w + b4.w;
    *(float4*)(Y + (size_t)row * DM + tid * 4) = y4;
}

// ---------------------------------------------------------------------------
extern "C" void kernel_launch(void* const* d_in, const int* in_sizes, int n_in,
                              void* d_out, int out_size)
{
    (void)in_sizes; (void)n_in; (void)out_size;
    const float* Q    = (const float*)d_in[0];
    const float* K    = (const float*)d_in[1];
    const float* V    = (const float*)d_in[2];
    const int*   mask = (const int*)  d_in[3];
    const float* Wq   = (const float*)d_in[4];
    const float* bq   = (const float*)d_in[5];
    const float* Wk   = (const float*)d_in[6];
    const float* bk   = (const float*)d_in[7];
    const float* Wv   = (const float*)d_in[8];
    const float* bv   = (const float*)d_in[9];
    const float* Wo   = (const float*)d_in[10];
    const float* bo   = (const float*)d_in[11];
    const float* lg   = (const float*)d_in[12];
    const float* lb   = (const float*)d_in[13];

    float* y    = (float*)d_out;
    float* attn = y + YSZ;

    bf16 *xh, *x2h, *x3h, *wh, *w2h, *w3h, *woh, *ch;
    bf16 *qh, *ql, *kh, *vh;
    float *po;
    cudaGetSymbolAddress((void**)&xh,  g_xh);
    cudaGetSymbolAddress((void**)&x2h, g_x2h);
    cudaGetSymbolAddress((void**)&x3h, g_x3h);
    cudaGetSymbolAddress((void**)&wh,  g_wh);
    cudaGetSymbolAddress((void**)&w2h, g_w2h);
    cudaGetSymbolAddress((void**)&w3h, g_w3h);
    cudaGetSymbolAddress((void**)&woh, g_woh);
    cudaGetSymbolAddress((void**)&ch,  g_ch);
    cudaGetSymbolAddress((void**)&qh,  g_qh);
    cudaGetSymbolAddress((void**)&ql,  g_ql);
    cudaGetSymbolAddress((void**)&kh,  g_kh);
    cudaGetSymbolAddress((void**)&vh,  g_vh);
    cudaGetSymbolAddress((void**)&po,  g_o);

    const int SM_PROJ  = 65536 + 128;
    const int SM_SCORE = 49152 + 1024;
    const int SM_CTX   = 49152 + 1024;
    cudaFuncSetAttribute(proj16,  cudaFuncAttributeMaxDynamicSharedMemorySize, SM_PROJ);
    cudaFuncSetAttribute(score16, cudaFuncAttributeMaxDynamicSharedMemorySize, SM_SCORE);
    cudaFuncSetAttribute(ctx_mma, cudaFuncAttributeMaxDynamicSharedMemorySize, SM_CTX);

    const int gx = (MROWS * DM / 4) / 256;
    const int gw = (DM * DM / 4) / 256;
    dim3 gp(DM / 128, MROWS / 128);          // (8, 64)

    conv_h<<<gw, 256>>>(Wq, wh);
    conv_h<<<gx, 256>>>(Q, xh);
    conv_h<<<gw, 256>>>(Wk, w2h);
    conv_h<<<gx, 256>>>(K, x2h);
    conv_h<<<gw, 256>>>(Wv, w3h);
    proj16<<<gp, 256, SM_PROJ>>>(xh, wh, bq, nullptr, qh, ql);
    conv_h<<<gx, 256>>>(V, x3h);
    conv_h<<<gw, 256>>>(Wo, woh);
    zero_rsum_kernel<<<(NB * NH * SQ) / 256, 256>>>();
    proj16<<<gp, 256, SM_PROJ>>>(x2h, w2h, bk, nullptr, kh, nullptr);
    proj16<<<gp, 256, SM_PROJ>>>(x3h, w3h, bv, nullptr, vh, nullptr);

    dim3 gs(SQ / 128, SQ / 128, NB * NH);    // (16, 16, 64)
    score16<<<gs, 256, SM_SCORE>>>(mask);

    dim3 gc(1, SQ / 128, NB * NH);           // (1, 16, 64)
    ctx_mma<<<gc, 256, SM_CTX>>>(attn);

    proj16<<<gp, 256, SM_PROJ>>>(ch, woh, bo, po, nullptr, nullptr);

    ln_kernel<<<MROWS, 256>>>(Q, lg, lb, y);
}